// round 2
// baseline (speedup 1.0000x reference)
#include <cuda_runtime.h>
#include <math.h>

#define B_   2
#define L_   2048
#define H_   16
#define D_   64
#define HID_ 1024
#define NB_  4
#define BL_  (B_*L_)      /* 4096  */
#define TH_  (BL_*H_)     /* 65536 */
#define NH_  128          /* gate hidden width = 2*D */

// ---------------- scratch (no allocations allowed) ----------------
__device__ float g_S[12 * NH_];        // column sums of W1 stat blocks
__device__ float g_C1[BL_ * NH_];      // hidden @ W1[0:1024]  (2 MB)
__device__ float g_stats[TH_ * 12];    // per-(th) stat scalars (3 MB)

// ---------------- kernel P: stat-block column sums ----------------
// S[s][o] = sum_{d<64} W1[1024 + s*64 + d][o]
__global__ void prep_S_kernel(const float* __restrict__ W1) {
    int s = blockIdx.x;       // 0..11
    int o = threadIdx.x;      // 0..127
    const float* base = W1 + (size_t)(HID_ + s * 64) * NH_ + o;
    float acc = 0.f;
#pragma unroll
    for (int d = 0; d < 64; d++) acc += base[d * NH_];
    g_S[s * NH_ + o] = acc;
}

// ---------------- kernel S: per token-head stats ----------------
// one warp per th; stats[th][p*3+{0,1,2}] = mean, rms, max of branch_p[th][:]
__global__ void stats_kernel(const float* __restrict__ br0,
                             const float* __restrict__ br1,
                             const float* __restrict__ br2,
                             const float* __restrict__ br3) {
    int th   = blockIdx.x * (blockDim.x >> 5) + (threadIdx.x >> 5);
    int lane = threadIdx.x & 31;
    if (th >= TH_) return;
#pragma unroll
    for (int p = 0; p < 4; p++) {
        const float* bp = (p == 0) ? br0 : (p == 1) ? br1 : (p == 2) ? br2 : br3;
        float x0 = bp[(size_t)th * 64 + lane];
        float x1 = bp[(size_t)th * 64 + 32 + lane];
        float sum = x0 + x1;
        float sq  = x0 * x0 + x1 * x1;
        float mx  = fmaxf(x0, x1);
#pragma unroll
        for (int off = 16; off; off >>= 1) {
            sum += __shfl_xor_sync(0xFFFFFFFFu, sum, off);
            sq  += __shfl_xor_sync(0xFFFFFFFFu, sq,  off);
            mx   = fmaxf(mx, __shfl_xor_sync(0xFFFFFFFFu, mx, off));
        }
        if (lane == 0) {
            float* st = g_stats + (size_t)th * 12 + p * 3;
            st[0] = sum * (1.0f / 64.0f);
            st[1] = sqrtf(fmaxf(sq * (1.0f / 64.0f), 1e-8f));
            st[2] = mx;
        }
    }
}

// ---------------- kernel G1: C1 = hidden @ W1[0:1024] ----------------
// M=4096, K=1024, N=128. 64x64 tiles, 256 threads, 4x4 micro-tile.
__global__ void __launch_bounds__(256) g1_kernel(const float* __restrict__ hidden,
                                                 const float* __restrict__ W1) {
    __shared__ float As[32][68];
    __shared__ float Bs[32][68];
    int tid = threadIdx.x;
    int m0 = blockIdx.x * 64;   // over 4096
    int n0 = blockIdx.y * 64;   // over 128
    int ty = tid >> 4, tx = tid & 15;
    float acc[4][4] = {};

    for (int c = 0; c < 32; c++) {
        int k0 = c * 32;
#pragma unroll
        for (int e = 0; e < 8; e++) {
            int idx = e * 256 + tid;
            int m = idx >> 5, k = idx & 31;
            As[k][m] = hidden[(size_t)(m0 + m) * HID_ + k0 + k];
        }
#pragma unroll
        for (int e = 0; e < 8; e++) {
            int idx = e * 256 + tid;
            int k = idx >> 6, n = idx & 63;
            Bs[k][n] = W1[(size_t)(k0 + k) * NH_ + n0 + n];
        }
        __syncthreads();
#pragma unroll
        for (int kk = 0; kk < 32; kk++) {
            float4 av = *(const float4*)&As[kk][ty * 4];
            float4 bv = *(const float4*)&Bs[kk][tx * 4];
            float a[4] = {av.x, av.y, av.z, av.w};
            float b[4] = {bv.x, bv.y, bv.z, bv.w};
#pragma unroll
            for (int i = 0; i < 4; i++)
#pragma unroll
                for (int j = 0; j < 4; j++)
                    acc[i][j] = fmaf(a[i], b[j], acc[i][j]);
        }
        __syncthreads();
    }
#pragma unroll
    for (int i = 0; i < 4; i++)
#pragma unroll
        for (int j = 0; j < 4; j++)
            g_C1[(size_t)(m0 + ty * 4 + i) * NH_ + n0 + tx * 4 + j] = acc[i][j];
}

// ---------------- kernel G2: branch GEMM + fused epilogue ----------------
// 128 token-heads x 128 outputs per block, K=256 (8 chunks of 32),
// 256 threads, 8x8 micro-tile. Epilogue: +stats rank-12, +C1, +b1, gelu,
// @W2 (+b2), temp-softmax, floor, renorm, float4 store.
__global__ void __launch_bounds__(256) g2_kernel(const float* __restrict__ br0,
                                                 const float* __restrict__ br1,
                                                 const float* __restrict__ br2,
                                                 const float* __restrict__ br3,
                                                 const float* __restrict__ W1,
                                                 const float* __restrict__ b1,
                                                 const float* __restrict__ W2,
                                                 const float* __restrict__ b2v,
                                                 const float* __restrict__ eps_floor,
                                                 const float* __restrict__ temp,
                                                 float* __restrict__ out) {
    __shared__ float As[32][132];
    __shared__ float Bs[32][132];
    __shared__ float Ssm[12][NH_];
    __shared__ float w2s[NH_ * 4];
    __shared__ float slog[128][4];

    int tid = threadIdx.x;
    int th0 = blockIdx.x * 128;
    int ty = tid >> 4, tx = tid & 15;

    for (int i = tid; i < 12 * NH_; i += 256) Ssm[i >> 7][i & 127] = g_S[i];
    for (int i = tid; i < NH_ * 4; i += 256) w2s[i] = W2[i];

    float acc[8][8] = {};

#pragma unroll
    for (int c = 0; c < 8; c++) {
        const float* bp = (c < 2) ? br0 : (c < 4) ? br1 : (c < 6) ? br2 : br3;
        int koff = (c & 1) * 32;
        int krow0 = HID_ + 12 * 64 + c * 32;   // 1792 + c*32
#pragma unroll
        for (int e = 0; e < 16; e++) {
            int idx = e * 256 + tid;
            int m = idx >> 5, k = idx & 31;
            As[k][m] = bp[(size_t)(th0 + m) * 64 + koff + k];
        }
#pragma unroll
        for (int e = 0; e < 16; e++) {
            int idx = e * 256 + tid;
            int k = idx >> 7, n = idx & 127;
            Bs[k][n] = W1[(size_t)(krow0 + k) * NH_ + n];
        }
        __syncthreads();
#pragma unroll
        for (int kk = 0; kk < 32; kk++) {
            float4 a0 = *(const float4*)&As[kk][ty * 8];
            float4 a1 = *(const float4*)&As[kk][ty * 8 + 4];
            float4 b0 = *(const float4*)&Bs[kk][tx * 8];
            float4 b1v_ = *(const float4*)&Bs[kk][tx * 8 + 4];
            float a[8] = {a0.x, a0.y, a0.z, a0.w, a1.x, a1.y, a1.z, a1.w};
            float b[8] = {b0.x, b0.y, b0.z, b0.w, b1v_.x, b1v_.y, b1v_.z, b1v_.w};
#pragma unroll
            for (int i = 0; i < 8; i++)
#pragma unroll
                for (int j = 0; j < 8; j++)
                    acc[i][j] = fmaf(a[i], b[j], acc[i][j]);
        }
        __syncthreads();
    }

    // ---- epilogue ----
    float b1r[8];
#pragma unroll
    for (int j = 0; j < 8; j++) b1r[j] = b1[tx * 8 + j];

#pragma unroll
    for (int i = 0; i < 8; i++) {
        int th = th0 + ty * 8 + i;
        int bl = th >> 4;
        float z[8];
        const float4* c1p = (const float4*)&g_C1[(size_t)bl * NH_ + tx * 8];
        float4 c1a = c1p[0], c1b = c1p[1];
        float c1r[8] = {c1a.x, c1a.y, c1a.z, c1a.w, c1b.x, c1b.y, c1b.z, c1b.w};
#pragma unroll
        for (int j = 0; j < 8; j++) z[j] = acc[i][j] + b1r[j] + c1r[j];
        const float* st = g_stats + (size_t)th * 12;
#pragma unroll
        for (int s = 0; s < 12; s++) {
            float sv = st[s];
#pragma unroll
            for (int j = 0; j < 8; j++)
                z[j] = fmaf(sv, Ssm[s][tx * 8 + j], z[j]);
        }
        float pl[4] = {0.f, 0.f, 0.f, 0.f};
#pragma unroll
        for (int j = 0; j < 8; j++) {
            float x = z[j];
            float h1v = 0.5f * x * (1.0f + erff(x * 0.7071067811865475f));
            int o = tx * 8 + j;
#pragma unroll
            for (int c4 = 0; c4 < 4; c4++)
                pl[c4] = fmaf(h1v, w2s[o * 4 + c4], pl[c4]);
        }
        // reduce over the 16 tx lanes (half-warp; lane = (ty&1)*16 + tx)
#pragma unroll
        for (int off = 8; off >= 1; off >>= 1)
#pragma unroll
            for (int c4 = 0; c4 < 4; c4++)
                pl[c4] += __shfl_xor_sync(0xFFFFFFFFu, pl[c4], off);
        if (tx == 0) {
#pragma unroll
            for (int c4 = 0; c4 < 4; c4++)
                slog[ty * 8 + i][c4] = pl[c4] + b2v[c4];
        }
    }
    __syncthreads();

    if (tid < 128) {
        int th = th0 + tid;
        int h  = th & (H_ - 1);
        float t = fminf(fmaxf(temp[h], 0.2f), 10.0f);
        float inv_t = 1.0f / t;
        float l0 = slog[tid][0], l1 = slog[tid][1], l2 = slog[tid][2], l3 = slog[tid][3];
        float mx = fmaxf(fmaxf(l0, l1), fmaxf(l2, l3));
        float e0 = expf((l0 - mx) * inv_t);
        float e1 = expf((l1 - mx) * inv_t);
        float e2 = expf((l2 - mx) * inv_t);
        float e3 = expf((l3 - mx) * inv_t);
        float inv = 1.0f / (e0 + e1 + e2 + e3);
        float w0 = e0 * inv, w1 = e1 * inv, w2 = e2 * inv, w3 = e3 * inv;
        float f0 = fminf(fmaxf(eps_floor[h * 4 + 0], 1e-7f), 0.1f);
        float f1 = fminf(fmaxf(eps_floor[h * 4 + 1], 1e-7f), 0.1f);
        float f2 = fminf(fmaxf(eps_floor[h * 4 + 2], 1e-7f), 0.1f);
        float f3 = fminf(fmaxf(eps_floor[h * 4 + 3], 1e-7f), 0.1f);
        w0 = fmaxf(w0, f0); w1 = fmaxf(w1, f1); w2 = fmaxf(w2, f2); w3 = fmaxf(w3, f3);
        float inv2 = 1.0f / (w0 + w1 + w2 + w3);
        ((float4*)out)[th] = make_float4(w0 * inv2, w1 * inv2, w2 * inv2, w3 * inv2);
    }
}

// ---------------- launch ----------------
extern "C" void kernel_launch(void* const* d_in, const int* in_sizes, int n_in,
                              void* d_out, int out_size) {
    const float* hidden = (const float*)d_in[0];
    const float* br0    = (const float*)d_in[1];
    const float* br1    = (const float*)d_in[2];
    const float* br2    = (const float*)d_in[3];
    const float* br3    = (const float*)d_in[4];
    const float* W1     = (const float*)d_in[5];
    const float* b1     = (const float*)d_in[6];
    const float* W2     = (const float*)d_in[7];
    const float* b2v    = (const float*)d_in[8];
    const float* epsf   = (const float*)d_in[9];
    const float* temp   = (const float*)d_in[10];
    float* out = (float*)d_out;

    prep_S_kernel<<<12, 128>>>(W1);
    stats_kernel<<<TH_ / 8, 256>>>(br0, br1, br2, br3);
    g1_kernel<<<dim3(BL_ / 64, 2), 256>>>(hidden, W1);
    g2_kernel<<<TH_ / 128, 256>>>(br0, br1, br2, br3, W1, b1, W2, b2v,
                                  epsf, temp, out);
}

// round 5
// speedup vs baseline: 1.0719x; 1.0719x over previous
#include <cuda_runtime.h>
#include <math.h>

#define B_   2
#define L_   2048
#define H_   16
#define D_   64
#define HID_ 1024
#define NB_  4
#define BL_  (B_*L_)      /* 4096  */
#define TH_  (BL_*H_)     /* 65536 */
#define NH_  128          /* gate hidden width = 2*D */

// ---------------- scratch (no allocations allowed) ----------------
__device__ float g_S[12 * NH_];        // column sums of W1 stat blocks
__device__ float g_C1[BL_ * NH_];      // hidden @ W1[0:1024]  (2 MB)
__device__ float g_stats[TH_ * 12];    // per-(th) stat scalars (3 MB)
__device__ float g_Z[(size_t)TH_ * NH_]; // branch GEMM result (33.5 MB)

// ---------------- kernel P: stat-block column sums ----------------
__global__ void prep_S_kernel(const float* __restrict__ W1) {
    int s = blockIdx.x;       // 0..11
    int o = threadIdx.x;      // 0..127
    const float* base = W1 + (size_t)(HID_ + s * 64) * NH_ + o;
    float acc = 0.f;
#pragma unroll
    for (int d = 0; d < 64; d++) acc += base[d * NH_];
    g_S[s * NH_ + o] = acc;
}

// ---------------- kernel S: per token-head stats ----------------
__global__ void stats_kernel(const float* __restrict__ br0,
                             const float* __restrict__ br1,
                             const float* __restrict__ br2,
                             const float* __restrict__ br3) {
    int th   = blockIdx.x * (blockDim.x >> 5) + (threadIdx.x >> 5);
    int lane = threadIdx.x & 31;
    if (th >= TH_) return;
#pragma unroll
    for (int p = 0; p < 4; p++) {
        const float* bp = (p == 0) ? br0 : (p == 1) ? br1 : (p == 2) ? br2 : br3;
        float x0 = bp[(size_t)th * 64 + lane];
        float x1 = bp[(size_t)th * 64 + 32 + lane];
        float sum = x0 + x1;
        float sq  = x0 * x0 + x1 * x1;
        float mx  = fmaxf(x0, x1);
#pragma unroll
        for (int off = 16; off; off >>= 1) {
            sum += __shfl_xor_sync(0xFFFFFFFFu, sum, off);
            sq  += __shfl_xor_sync(0xFFFFFFFFu, sq,  off);
            mx   = fmaxf(mx, __shfl_xor_sync(0xFFFFFFFFu, mx, off));
        }
        if (lane == 0) {
            float* st = g_stats + (size_t)th * 12 + p * 3;
            st[0] = sum * (1.0f / 64.0f);
            st[1] = sqrtf(fmaxf(sq * (1.0f / 64.0f), 1e-8f));
            st[2] = mx;
        }
    }
}

// ---------------- kernel G1: C1 = hidden @ W1[0:1024] ----------------
__global__ void __launch_bounds__(256) g1_kernel(const float* __restrict__ hidden,
                                                 const float* __restrict__ W1) {
    __shared__ float As[32][68];
    __shared__ float Bs[32][68];
    int tid = threadIdx.x;
    int m0 = blockIdx.x * 64;
    int n0 = blockIdx.y * 64;
    int ty = tid >> 4, tx = tid & 15;
    float acc[4][4] = {};

    for (int c = 0; c < 32; c++) {
        int k0 = c * 32;
#pragma unroll
        for (int e = 0; e < 8; e++) {
            int idx = e * 256 + tid;
            int m = idx >> 5, k = idx & 31;
            As[k][m] = hidden[(size_t)(m0 + m) * HID_ + k0 + k];
        }
#pragma unroll
        for (int e = 0; e < 8; e++) {
            int idx = e * 256 + tid;
            int k = idx >> 6, n = idx & 63;
            Bs[k][n] = W1[(size_t)(k0 + k) * NH_ + n0 + n];
        }
        __syncthreads();
#pragma unroll
        for (int kk = 0; kk < 32; kk++) {
            float4 av = *(const float4*)&As[kk][ty * 4];
            float4 bv = *(const float4*)&Bs[kk][tx * 4];
            float a[4] = {av.x, av.y, av.z, av.w};
            float b[4] = {bv.x, bv.y, bv.z, bv.w};
#pragma unroll
            for (int i = 0; i < 4; i++)
#pragma unroll
                for (int j = 0; j < 4; j++)
                    acc[i][j] = fmaf(a[i], b[j], acc[i][j]);
        }
        __syncthreads();
    }
#pragma unroll
    for (int i = 0; i < 4; i++)
#pragma unroll
        for (int j = 0; j < 4; j++)
            g_C1[(size_t)(m0 + ty * 4 + i) * NH_ + n0 + tx * 4 + j] = acc[i][j];
}

// ---------------- kernel G2: pure branch GEMM -> g_Z ----------------
// 128 token-heads x 128 outputs per block, K=256 (8 chunks of 32),
// 256 threads, 8x8 micro-tile. NO epilogue (register pressure isolation).
__global__ void __launch_bounds__(256, 2) g2g_kernel(const float* __restrict__ br0,
                                                     const float* __restrict__ br1,
                                                     const float* __restrict__ br2,
                                                     const float* __restrict__ br3,
                                                     const float* __restrict__ W1) {
    __shared__ float As[32][132];
    __shared__ float Bs[32][132];

    int tid = threadIdx.x;
    int th0 = blockIdx.x * 128;
    int ty = tid >> 4, tx = tid & 15;

    float acc[8][8] = {};

#pragma unroll
    for (int c = 0; c < 8; c++) {
        const float* bp = (c < 2) ? br0 : (c < 4) ? br1 : (c < 6) ? br2 : br3;
        int koff = (c & 1) * 32;
        int krow0 = HID_ + 12 * 64 + c * 32;   // 1792 + c*32
#pragma unroll
        for (int e = 0; e < 16; e++) {
            int idx = e * 256 + tid;
            int m = idx >> 5, k = idx & 31;
            As[k][m] = bp[(size_t)(th0 + m) * 64 + koff + k];
        }
#pragma unroll
        for (int e = 0; e < 16; e++) {
            int idx = e * 256 + tid;
            int k = idx >> 7, n = idx & 127;
            Bs[k][n] = W1[(size_t)(krow0 + k) * NH_ + n];
        }
        __syncthreads();
#pragma unroll
        for (int kk = 0; kk < 32; kk++) {
            float4 a0 = *(const float4*)&As[kk][ty * 8];
            float4 a1 = *(const float4*)&As[kk][ty * 8 + 4];
            float4 b0 = *(const float4*)&Bs[kk][tx * 8];
            float4 b1v = *(const float4*)&Bs[kk][tx * 8 + 4];
            float a[8] = {a0.x, a0.y, a0.z, a0.w, a1.x, a1.y, a1.z, a1.w};
            float b[8] = {b0.x, b0.y, b0.z, b0.w, b1v.x, b1v.y, b1v.z, b1v.w};
#pragma unroll
            for (int i = 0; i < 8; i++)
#pragma unroll
                for (int j = 0; j < 8; j++)
                    acc[i][j] = fmaf(a[i], b[j], acc[i][j]);
        }
        __syncthreads();
    }

#pragma unroll
    for (int i = 0; i < 8; i++) {
        size_t row = (size_t)(th0 + ty * 8 + i);
        *(float4*)&g_Z[row * NH_ + tx * 8]     = make_float4(acc[i][0], acc[i][1], acc[i][2], acc[i][3]);
        *(float4*)&g_Z[row * NH_ + tx * 8 + 4] = make_float4(acc[i][4], acc[i][5], acc[i][6], acc[i][7]);
    }
}

// ---------------- kernel E: epilogue (one warp per token-head) ----------------
__global__ void __launch_bounds__(256) epi_kernel(const float* __restrict__ b1,
                                                  const float* __restrict__ W2,
                                                  const float* __restrict__ b2v,
                                                  const float* __restrict__ eps_floor,
                                                  const float* __restrict__ temp,
                                                  float* __restrict__ out) {
    int th   = blockIdx.x * 8 + (threadIdx.x >> 5);
    int lane = threadIdx.x & 31;
    if (th >= TH_) return;
    int bl = th >> 4;
    int h  = th & (H_ - 1);

    float stl[12];
    {
        const float* st = g_stats + (size_t)th * 12;
#pragma unroll
        for (int s = 0; s < 12; s++) stl[s] = st[s];
    }

    float pl0 = 0.f, pl1 = 0.f, pl2 = 0.f, pl3 = 0.f;
#pragma unroll
    for (int t = 0; t < 4; t++) {
        int o = lane + 32 * t;
        float z = g_Z[(size_t)th * NH_ + o] + g_C1[(size_t)bl * NH_ + o] + __ldg(&b1[o]);
#pragma unroll
        for (int s = 0; s < 12; s++)
            z = fmaf(stl[s], g_S[s * NH_ + o], z);
        float h1v = 0.5f * z * (1.0f + erff(z * 0.7071067811865475f));
        pl0 = fmaf(h1v, __ldg(&W2[o * 4 + 0]), pl0);
        pl1 = fmaf(h1v, __ldg(&W2[o * 4 + 1]), pl1);
        pl2 = fmaf(h1v, __ldg(&W2[o * 4 + 2]), pl2);
        pl3 = fmaf(h1v, __ldg(&W2[o * 4 + 3]), pl3);
    }
#pragma unroll
    for (int off = 16; off; off >>= 1) {
        pl0 += __shfl_xor_sync(0xFFFFFFFFu, pl0, off);
        pl1 += __shfl_xor_sync(0xFFFFFFFFu, pl1, off);
        pl2 += __shfl_xor_sync(0xFFFFFFFFu, pl2, off);
        pl3 += __shfl_xor_sync(0xFFFFFFFFu, pl3, off);
    }
    if (lane == 0) {
        float l0 = pl0 + b2v[0], l1 = pl1 + b2v[1], l2 = pl2 + b2v[2], l3 = pl3 + b2v[3];
        float t = fminf(fmaxf(temp[h], 0.2f), 10.0f);
        float inv_t = 1.0f / t;
        float mx = fmaxf(fmaxf(l0, l1), fmaxf(l2, l3));
        float e0 = expf((l0 - mx) * inv_t);
        float e1 = expf((l1 - mx) * inv_t);
        float e2 = expf((l2 - mx) * inv_t);
        float e3 = expf((l3 - mx) * inv_t);
        float inv = 1.0f / (e0 + e1 + e2 + e3);
        float w0 = e0 * inv, w1 = e1 * inv, w2 = e2 * inv, w3 = e3 * inv;
        float f0 = fminf(fmaxf(eps_floor[h * 4 + 0], 1e-7f), 0.1f);
        float f1 = fminf(fmaxf(eps_floor[h * 4 + 1], 1e-7f), 0.1f);
        float f2 = fminf(fmaxf(eps_floor[h * 4 + 2], 1e-7f), 0.1f);
        float f3 = fminf(fmaxf(eps_floor[h * 4 + 3], 1e-7f), 0.1f);
        w0 = fmaxf(w0, f0); w1 = fmaxf(w1, f1); w2 = fmaxf(w2, f2); w3 = fmaxf(w3, f3);
        float inv2 = 1.0f / (w0 + w1 + w2 + w3);
        ((float4*)out)[th] = make_float4(w0 * inv2, w1 * inv2, w2 * inv2, w3 * inv2);
    }
}

// ---------------- launch ----------------
extern "C" void kernel_launch(void* const* d_in, const int* in_sizes, int n_in,
                              void* d_out, int out_size) {
    const float* hidden = (const float*)d_in[0];
    const float* br0    = (const float*)d_in[1];
    const float* br1    = (const float*)d_in[2];
    const float* br2    = (const float*)d_in[3];
    const float* br3    = (const float*)d_in[4];
    const float* W1     = (const float*)d_in[5];
    const float* b1     = (const float*)d_in[6];
    const float* W2     = (const float*)d_in[7];
    const float* b2v    = (const float*)d_in[8];
    const float* epsf   = (const float*)d_in[9];
    const float* temp   = (const float*)d_in[10];
    float* out = (float*)d_out;

    prep_S_kernel<<<12, 128>>>(W1);
    stats_kernel<<<TH_ / 8, 256>>>(br0, br1, br2, br3);
    g1_kernel<<<dim3(BL_ / 64, 2), 256>>>(hidden, W1);
    g2g_kernel<<<TH_ / 128, 256>>>(br0, br1, br2, br3, W1);
    epi_kernel<<<TH_ / 8, 256>>>(b1, W2, b2v, epsf, temp, out);
}

// round 8
// speedup vs baseline: 1.8089x; 1.6876x over previous
#include <cuda_runtime.h>
#include <cuda_bf16.h>
#include <math.h>
#include <stdint.h>

#define H_   16
#define HID_ 1024
#define BL_  4096      /* B*L   */
#define TH_  65536     /* B*L*H */
#define NH_  128       /* gate hidden = 2*D */
#define KTOT 2048      /* W1 rows */

// ---------------- device scratch (no allocations) ----------------
__device__ __nv_bfloat16 g_W1Thi[NH_ * KTOT];   // W1^T hi  [n][k]
__device__ __nv_bfloat16 g_W1Tlo[NH_ * KTOT];   // W1^T lo
__device__ float g_S[12 * NH_];                 // stat-block column sums
__device__ float g_C1[BL_ * NH_];               // hidden @ W1[:1024]  [bl][col]

// B smem staging: [buf][split][n=128][48 bytes]  (16 k bf16 used, 48B stride = conflict-free)
#define SB_NSTRIDE 48
#define SB_SPLIT   (NH_ * SB_NSTRIDE)     /* 6144  */
#define SB_BUF     (2 * SB_SPLIT)         /* 12288 */

// ---------------- helpers ----------------
__device__ __forceinline__ uint32_t packbf2(float x, float y) {
    __nv_bfloat162 t = __floats2bfloat162_rn(x, y);
    return *(uint32_t*)&t;
}
__device__ __forceinline__ void mma16816(float* d, const uint32_t* a, uint32_t b0, uint32_t b1) {
    asm volatile(
        "mma.sync.aligned.m16n8k16.row.col.f32.bf16.bf16.f32 "
        "{%0,%1,%2,%3}, {%4,%5,%6,%7}, {%8,%9}, {%0,%1,%2,%3};"
        : "+f"(d[0]), "+f"(d[1]), "+f"(d[2]), "+f"(d[3])
        : "r"(a[0]), "r"(a[1]), "r"(a[2]), "r"(a[3]), "r"(b0), "r"(b1));
}
// split one float2 pair into hi/lo bf16x2 packs
__device__ __forceinline__ void split2(float x, float y, uint32_t& hi, uint32_t& lo) {
    __nv_bfloat16 hx = __float2bfloat16_rn(x);
    __nv_bfloat16 hy = __float2bfloat16_rn(y);
    hi = packbf2(__bfloat162float(hx), __bfloat162float(hy));  // exact re-pack
    __nv_bfloat162 hh = __halves2bfloat162(hx, hy);
    hi = *(uint32_t*)&hh;
    lo = packbf2(x - __bfloat162float(hx), y - __bfloat162float(hy));
}

// ---------------- prep kernels ----------------
__global__ void prep_S_kernel(const float* __restrict__ W1) {
    int s = blockIdx.x;       // 0..11
    int o = threadIdx.x;      // 0..127
    const float* base = W1 + (size_t)(HID_ + s * 64) * NH_ + o;
    float acc = 0.f;
#pragma unroll
    for (int d = 0; d < 64; d++) acc += base[d * NH_];
    g_S[s * NH_ + o] = acc;
}

// transpose + bf16 hi/lo split:  W1T[n][k] = W1[k][n]
__global__ void prep_w1t_kernel(const float* __restrict__ W1) {
    __shared__ float sm[32][33];
    int k0 = blockIdx.x * 32, n0 = blockIdx.y * 32;
    int tx = threadIdx.x, ty = threadIdx.y;
    sm[ty][tx] = W1[(size_t)(k0 + ty) * NH_ + n0 + tx];
    __syncthreads();
    float x = sm[tx][ty];               // = W1[k0+tx][n0+ty]
    __nv_bfloat16 h = __float2bfloat16_rn(x);
    float lo = x - __bfloat162float(h);
    size_t idx = (size_t)(n0 + ty) * KTOT + k0 + tx;
    g_W1Thi[idx] = h;
    g_W1Tlo[idx] = __float2bfloat16_rn(lo);
}

// stage one k-step (16 k) of B (hi+lo) into smem buffer
__device__ __forceinline__ void stage_B_256(char* sB, int buf, int kbase, int tid) {
    int n = tid & 127, split = tid >> 7;   // 256 threads
    const __nv_bfloat16* src = (split ? g_W1Tlo : g_W1Thi) + (size_t)n * KTOT + kbase;
    const uint4* s4 = (const uint4*)src;
    uint4* d4 = (uint4*)(sB + buf * SB_BUF + split * SB_SPLIT + n * SB_NSTRIDE);
    d4[0] = s4[0];
    d4[1] = s4[1];
}
__device__ __forceinline__ void stage_B_128(char* sB, int buf, int kbase, int tid) {
    int n = tid;                            // 128 threads, both splits
#pragma unroll
    for (int split = 0; split < 2; split++) {
        const __nv_bfloat16* src = (split ? g_W1Tlo : g_W1Thi) + (size_t)n * KTOT + kbase;
        const uint4* s4 = (const uint4*)src;
        uint4* d4 = (uint4*)(sB + buf * SB_BUF + split * SB_SPLIT + n * SB_NSTRIDE);
        d4[0] = s4[0];
        d4[1] = s4[1];
    }
}

// compute one k-step: A frags already built; 16 n-tiles x 3 passes
__device__ __forceinline__ void kstep_mma(float acc[16][4], const char* sB, int buf,
                                          const uint32_t Ah[4], const uint32_t Al[4],
                                          int lane) {
    int q = lane & 3, r4 = lane >> 2;
    const char* bh = sB + buf * SB_BUF + r4 * SB_NSTRIDE + q * 4;
    const char* bl = bh + SB_SPLIT;
#pragma unroll
    for (int j = 0; j < 16; j++) {
        uint32_t b0h = *(const uint32_t*)(bh + j * 8 * SB_NSTRIDE);
        uint32_t b1h = *(const uint32_t*)(bh + j * 8 * SB_NSTRIDE + 16);
        uint32_t b0l = *(const uint32_t*)(bl + j * 8 * SB_NSTRIDE);
        uint32_t b1l = *(const uint32_t*)(bl + j * 8 * SB_NSTRIDE + 16);
        mma16816(acc[j], Ah, b0h, b1h);
        mma16816(acc[j], Ah, b0l, b1l);
        mma16816(acc[j], Al, b0h, b1h);
    }
}

// build A fragments from two row pointers (already offset to this kstep's col base + q*2)
__device__ __forceinline__ void build_A(const float* rp0, const float* rp1,
                                        uint32_t Ah[4], uint32_t Al[4],
                                        float2& v00, float2& v01, float2& v10, float2& v11) {
    v00 = *(const float2*)(rp0);        // a0: row r,   k q*2,  q*2+1
    v10 = *(const float2*)(rp1);        // a1: row r+8
    v01 = *(const float2*)(rp0 + 8);    // a2: row r,   k+8
    v11 = *(const float2*)(rp1 + 8);    // a3: row r+8, k+8
    split2(v00.x, v00.y, Ah[0], Al[0]);
    split2(v10.x, v10.y, Ah[1], Al[1]);
    split2(v01.x, v01.y, Ah[2], Al[2]);
    split2(v11.x, v11.y, Ah[3], Al[3]);
}

// ---------------- g1: C1 = hidden @ W1[:, first 1024 rows] ----------------
// grid 64, block 128 (4 warps), warp tile 16 rows x 128 cols, K=1024
__global__ void __launch_bounds__(128) g1_mma(const float* __restrict__ hidden) {
    __shared__ char sB[2 * SB_BUF];
    int tid = threadIdx.x, w = tid >> 5, lane = tid & 31;
    int q = lane & 3, r4 = lane >> 2;
    int row0 = blockIdx.x * 64 + w * 16 + r4;   // global bl row (a0/a2)
    const float* rbase0 = hidden + (size_t)row0 * HID_ + q * 2;
    const float* rbase1 = rbase0 + 8 * HID_;

    float acc[16][4];
#pragma unroll
    for (int j = 0; j < 16; j++)
#pragma unroll
        for (int e = 0; e < 4; e++) acc[j][e] = 0.f;

    stage_B_128(sB, 0, 0, tid);
    __syncthreads();
#pragma unroll 1
    for (int kk = 0; kk < 64; kk++) {
        if (kk + 1 < 64) stage_B_128(sB, (kk + 1) & 1, (kk + 1) * 16, tid);
        uint32_t Ah[4], Al[4];
        float2 v00, v01, v10, v11;
        build_A(rbase0 + kk * 16, rbase1 + kk * 16, Ah, Al, v00, v01, v10, v11);
        kstep_mma(acc, sB, kk & 1, Ah, Al, lane);
        __syncthreads();
    }
    // store: d0,d1 -> row0, cols j*8+q*2; d2,d3 -> row0+8
#pragma unroll
    for (int j = 0; j < 16; j++) {
        *(float2*)&g_C1[(size_t)row0 * NH_ + j * 8 + q * 2]       = make_float2(acc[j][0], acc[j][1]);
        *(float2*)&g_C1[(size_t)(row0 + 8) * NH_ + j * 8 + q * 2] = make_float2(acc[j][2], acc[j][3]);
    }
}

// ---------------- g2: branch GEMM + fused stats + fused epilogue ----------------
// grid 512, block 256 (8 warps), warp tile 16 rows x 128 cols, K=256 (4 branches x 64)
__global__ void __launch_bounds__(256) g2_mma(const float* __restrict__ br0,
                                              const float* __restrict__ br1,
                                              const float* __restrict__ br2,
                                              const float* __restrict__ br3,
                                              const float* __restrict__ b1,
                                              const float* __restrict__ W2,
                                              const float* __restrict__ b2v,
                                              const float* __restrict__ epsf,
                                              const float* __restrict__ temp,
                                              float* __restrict__ out) {
    __shared__ char  sB[2 * SB_BUF];       // 24576
    __shared__ float sC1[8 * NH_];         // 4096 B
    __shared__ float sS[12 * NH_];         // 6144 B
    __shared__ float sB1[NH_];             // 512 B
    __shared__ float sW2[NH_ * 4];         // 2048 B
    __shared__ float sST[128 * 12];        // 6144 B

    int tid = threadIdx.x, w = tid >> 5, lane = tid & 31;
    int q = lane & 3, r4 = lane >> 2;
    int th0 = blockIdx.x * 128;
    int rowc0 = w * 16 + r4;               // CTA-local row for a0/a2
    int grow0 = th0 + rowc0;

    // preload tables
    for (int i = tid; i < 8 * NH_; i += 256) sC1[i] = g_C1[(size_t)(th0 >> 4) * NH_ + i];
    for (int i = tid; i < 12 * NH_; i += 256) sS[i] = g_S[i];
    if (tid < NH_) sB1[tid] = b1[tid];
    for (int i = tid; i < NH_ * 4; i += 256) sW2[i] = W2[i];

    float acc[16][4];
#pragma unroll
    for (int j = 0; j < 16; j++)
#pragma unroll
        for (int e = 0; e < 4; e++) acc[j][e] = 0.f;

    stage_B_256(sB, 0, 1792, tid);
    __syncthreads();

    const float* brs0;
    const float* brs1;
#pragma unroll 1
    for (int p = 0; p < 4; p++) {
        const float* bp = (p == 0) ? br0 : (p == 1) ? br1 : (p == 2) ? br2 : br3;
        brs0 = bp + (size_t)grow0 * 64 + q * 2;
        brs1 = brs0 + 8 * 64;
        float sum0 = 0.f, sq0 = 0.f, mx0 = -3.402823466e38f;
        float sum1 = 0.f, sq1 = 0.f, mx1 = -3.402823466e38f;
#pragma unroll
        for (int k2 = 0; k2 < 4; k2++) {
            int kk = p * 4 + k2;
            if (kk + 1 < 16) stage_B_256(sB, (kk + 1) & 1, 1792 + (kk + 1) * 16, tid);
            uint32_t Ah[4], Al[4];
            float2 v00, v01, v10, v11;
            build_A(brs0 + k2 * 16, brs1 + k2 * 16, Ah, Al, v00, v01, v10, v11);
            sum0 += v00.x + v00.y + v01.x + v01.y;
            sq0 = fmaf(v00.x, v00.x, fmaf(v00.y, v00.y, fmaf(v01.x, v01.x, fmaf(v01.y, v01.y, sq0))));
            mx0 = fmaxf(mx0, fmaxf(fmaxf(v00.x, v00.y), fmaxf(v01.x, v01.y)));
            sum1 += v10.x + v10.y + v11.x + v11.y;
            sq1 = fmaf(v10.x, v10.x, fmaf(v10.y, v10.y, fmaf(v11.x, v11.x, fmaf(v11.y, v11.y, sq1))));
            mx1 = fmaxf(mx1, fmaxf(fmaxf(v10.x, v10.y), fmaxf(v11.x, v11.y)));
            kstep_mma(acc, sB, kk & 1, Ah, Al, lane);
            __syncthreads();
        }
        // reduce stats over the 4-lane group (lanes sharing a row)
#pragma unroll
        for (int m = 1; m <= 2; m <<= 1) {
            sum0 += __shfl_xor_sync(0xFFFFFFFFu, sum0, m);
            sq0  += __shfl_xor_sync(0xFFFFFFFFu, sq0,  m);
            mx0   = fmaxf(mx0, __shfl_xor_sync(0xFFFFFFFFu, mx0, m));
            sum1 += __shfl_xor_sync(0xFFFFFFFFu, sum1, m);
            sq1  += __shfl_xor_sync(0xFFFFFFFFu, sq1,  m);
            mx1   = fmaxf(mx1, __shfl_xor_sync(0xFFFFFFFFu, mx1, m));
        }
        if (q == 0) {
            float* st = sST + rowc0 * 12 + p * 3;
            st[0] = sum0 * (1.0f / 64.0f);
            st[1] = sqrtf(fmaxf(sq0 * (1.0f / 64.0f), 1e-8f));
            st[2] = mx0;
            float* st1 = sST + (rowc0 + 8) * 12 + p * 3;
            st1[0] = sum1 * (1.0f / 64.0f);
            st1[1] = sqrtf(fmaxf(sq1 * (1.0f / 64.0f), 1e-8f));
            st1[2] = mx1;
        }
    }
    __syncthreads();

    // ---- epilogue: per thread handles rows rowc0 (d0,d1) and rowc0+8 (d2,d3) ----
#pragma unroll
    for (int rr = 0; rr < 2; rr++) {
        int rowc = rowc0 + rr * 8;
        int bll = rowc >> 4;
        float stl[12];
#pragma unroll
        for (int s2 = 0; s2 < 12; s2++) stl[s2] = sST[rowc * 12 + s2];
        float pl0 = 0.f, pl1 = 0.f, pl2 = 0.f, pl3 = 0.f;
#pragma unroll
        for (int j = 0; j < 16; j++) {
#pragma unroll
            for (int e = 0; e < 2; e++) {
                int col = j * 8 + q * 2 + e;
                float z = acc[j][rr * 2 + e] + sC1[bll * NH_ + col] + sB1[col];
#pragma unroll
                for (int s2 = 0; s2 < 12; s2++)
                    z = fmaf(stl[s2], sS[s2 * NH_ + col], z);
                float g = 0.5f * z * (1.0f + erff(z * 0.70710678118654752440f));
                pl0 = fmaf(g, sW2[col * 4 + 0], pl0);
                pl1 = fmaf(g, sW2[col * 4 + 1], pl1);
                pl2 = fmaf(g, sW2[col * 4 + 2], pl2);
                pl3 = fmaf(g, sW2[col * 4 + 3], pl3);
            }
        }
#pragma unroll
        for (int m = 1; m <= 2; m <<= 1) {
            pl0 += __shfl_xor_sync(0xFFFFFFFFu, pl0, m);
            pl1 += __shfl_xor_sync(0xFFFFFFFFu, pl1, m);
            pl2 += __shfl_xor_sync(0xFFFFFFFFu, pl2, m);
            pl3 += __shfl_xor_sync(0xFFFFFFFFu, pl3, m);
        }
        if (q == 0) {
            int th = th0 + rowc;
            int h = th & (H_ - 1);
            float l0 = pl0 + b2v[0], l1 = pl1 + b2v[1], l2 = pl2 + b2v[2], l3 = pl3 + b2v[3];
            float t = fminf(fmaxf(temp[h], 0.2f), 10.0f);
            float inv_t = 1.0f / t;
            float mx = fmaxf(fmaxf(l0, l1), fmaxf(l2, l3));
            float e0 = expf((l0 - mx) * inv_t);
            float e1 = expf((l1 - mx) * inv_t);
            float e2 = expf((l2 - mx) * inv_t);
            float e3 = expf((l3 - mx) * inv_t);
            float inv = 1.0f / (e0 + e1 + e2 + e3);
            float w0 = e0 * inv, w1 = e1 * inv, w2 = e2 * inv, w3 = e3 * inv;
            float f0 = fminf(fmaxf(epsf[h * 4 + 0], 1e-7f), 0.1f);
            float f1 = fminf(fmaxf(epsf[h * 4 + 1], 1e-7f), 0.1f);
            float f2 = fminf(fmaxf(epsf[h * 4 + 2], 1e-7f), 0.1f);
            float f3 = fminf(fmaxf(epsf[h * 4 + 3], 1e-7f), 0.1f);
            w0 = fmaxf(w0, f0); w1 = fmaxf(w1, f1); w2 = fmaxf(w2, f2); w3 = fmaxf(w3, f3);
            float inv2 = 1.0f / (w0 + w1 + w2 + w3);
            ((float4*)out)[th] = make_float4(w0 * inv2, w1 * inv2, w2 * inv2, w3 * inv2);
        }
    }
}

// ---------------- launch ----------------
extern "C" void kernel_launch(void* const* d_in, const int* in_sizes, int n_in,
                              void* d_out, int out_size) {
    const float* hidden = (const float*)d_in[0];
    const float* br0    = (const float*)d_in[1];
    const float* br1    = (const float*)d_in[2];
    const float* br2    = (const float*)d_in[3];
    const float* br3    = (const float*)d_in[4];
    const float* W1     = (const float*)d_in[5];
    const float* b1     = (const float*)d_in[6];
    const float* W2     = (const float*)d_in[7];
    const float* b2v    = (const float*)d_in[8];
    const float* epsf   = (const float*)d_in[9];
    const float* temp   = (const float*)d_in[10];
    float* out = (float*)d_out;

    prep_S_kernel<<<12, 128>>>(W1);
    prep_w1t_kernel<<<dim3(KTOT / 32, NH_ / 32), dim3(32, 32)>>>(W1);
    g1_mma<<<BL_ / 64, 128>>>(hidden);
    g2_mma<<<TH_ / 128, 256>>>(br0, br1, br2, br3, b1, W2, b2v, epsf, temp, out);
}

// round 9
// speedup vs baseline: 2.8907x; 1.5981x over previous
#include <cuda_runtime.h>
#include <cuda_bf16.h>
#include <math.h>
#include <stdint.h>

#define H_   16
#define HID_ 1024
#define BL_  4096      /* B*L   */
#define TH_  65536     /* B*L*H */
#define NH_  128       /* gate hidden = 2*D */
#define KTOT 2048      /* W1 rows */
#define NKS  128       /* k-steps of 16 */

// ---------------- device scratch (no allocations) ----------------
// B packed in m16n8k16 fragment order: [ks][n][q] -> uint4 (b0h, b1h, b0l, b1l)
__device__ uint4 g_Bpk[NKS * NH_ * 4];          // 1 MB
__device__ float g_S[12 * NH_];                 // stat-block column sums
__device__ float g_C1a[BL_ * NH_];              // hidden @ W1[:512]
__device__ float g_C1b[BL_ * NH_];              // hidden @ W1[512:1024]

// ---------------- helpers ----------------
__device__ __forceinline__ uint32_t packbf2(float x, float y) {
    __nv_bfloat162 t = __floats2bfloat162_rn(x, y);
    return *(uint32_t*)&t;
}
__device__ __forceinline__ void split2(float x, float y, uint32_t& hi, uint32_t& lo) {
    __nv_bfloat16 hx = __float2bfloat16_rn(x);
    __nv_bfloat16 hy = __float2bfloat16_rn(y);
    __nv_bfloat162 hh = __halves2bfloat162(hx, hy);
    hi = *(uint32_t*)&hh;
    lo = packbf2(x - __bfloat162float(hx), y - __bfloat162float(hy));
}
__device__ __forceinline__ void mma16816(float* d, const uint32_t* a, uint32_t b0, uint32_t b1) {
    asm volatile(
        "mma.sync.aligned.m16n8k16.row.col.f32.bf16.bf16.f32 "
        "{%0,%1,%2,%3}, {%4,%5,%6,%7}, {%8,%9}, {%0,%1,%2,%3};"
        : "+f"(d[0]), "+f"(d[1]), "+f"(d[2]), "+f"(d[3])
        : "r"(a[0]), "r"(a[1]), "r"(a[2]), "r"(a[3]), "r"(b0), "r"(b1));
}
// A fragments for rows (r, r+8) at k-cols q*2(+1), q*2+8(+1); returns raw values too
__device__ __forceinline__ void build_A(const float* rp0, const float* rp1,
                                        uint32_t Ah[4], uint32_t Al[4],
                                        float2& v00, float2& v01, float2& v10, float2& v11) {
    v00 = *(const float2*)(rp0);
    v10 = *(const float2*)(rp1);
    v01 = *(const float2*)(rp0 + 8);
    v11 = *(const float2*)(rp1 + 8);
    split2(v00.x, v00.y, Ah[0], Al[0]);
    split2(v10.x, v10.y, Ah[1], Al[1]);
    split2(v01.x, v01.y, Ah[2], Al[2]);
    split2(v11.x, v11.y, Ah[3], Al[3]);
}
// stage one k-step (512 uint4 = 8 KB) into smem
__device__ __forceinline__ void stage(uint4* dst, int ks, int tid) {
    const uint4* src = g_Bpk + (size_t)ks * 512;
    dst[tid] = src[tid];
    dst[tid + 256] = src[tid + 256];
}

// ---------------- prep kernels ----------------
__global__ void prep_S_kernel(const float* __restrict__ W1) {
    int s = blockIdx.x;       // 0..11
    int o = threadIdx.x;      // 0..127
    const float* base = W1 + (size_t)(HID_ + s * 64) * NH_ + o;
    float acc = 0.f;
#pragma unroll
    for (int d = 0; d < 64; d++) acc += base[d * NH_];
    g_S[s * NH_ + o] = acc;
}

// pack W1 into fragment order
__global__ void prep_pack_kernel(const float* __restrict__ W1) {
    int t = blockIdx.x * 256 + threadIdx.x;   // 65536
    int q = t & 3, n = (t >> 2) & 127, ks = t >> 9;
    int k0 = ks * 16 + q * 2;
    float a0 = W1[(size_t)k0 * NH_ + n];
    float a1 = W1[(size_t)(k0 + 1) * NH_ + n];
    float a8 = W1[(size_t)(k0 + 8) * NH_ + n];
    float a9 = W1[(size_t)(k0 + 9) * NH_ + n];
    uint32_t h01, l01, h89, l89;
    split2(a0, a1, h01, l01);
    split2(a8, a9, h89, l89);
    g_Bpk[t] = make_uint4(h01, h89, l01, l89);
}

// ---------------- g1: C1 partials = hidden @ W1[k-half] ----------------
// grid (64, 2), block 256. CTA: 64 rows x 128 cols, K=512.
// warp w: row-group w>>1, col-half w&1.
__global__ void __launch_bounds__(256, 2) g1_mma(const float* __restrict__ hidden) {
    __shared__ uint4 sB[2][512];
    int tid = threadIdx.x, w = tid >> 5, lane = tid & 31;
    int q = lane & 3, r4 = lane >> 2;
    int rgrp = w >> 1, ch = w & 1;
    int bl0 = blockIdx.x * 64;
    int khalf = blockIdx.y;
    int ks0 = khalf * 32;
    int rowc0 = rgrp * 16 + r4;
    const float* rbase0 = hidden + (size_t)(bl0 + rowc0) * HID_ + khalf * 512 + q * 2;
    const float* rbase1 = rbase0 + 8 * HID_;

    float acc[8][4];
#pragma unroll
    for (int j = 0; j < 8; j++)
#pragma unroll
        for (int e = 0; e < 4; e++) acc[j][e] = 0.f;

    stage(sB[0], ks0, tid);
    __syncthreads();
#pragma unroll 1
    for (int kk = 0; kk < 32; kk++) {
        if (kk + 1 < 32) stage(sB[(kk + 1) & 1], ks0 + kk + 1, tid);
        uint32_t Ah[4], Al[4];
        float2 v00, v01, v10, v11;
        build_A(rbase0 + kk * 16, rbase1 + kk * 16, Ah, Al, v00, v01, v10, v11);
        const uint4* bp = sB[kk & 1] + ch * 256 + lane;
#pragma unroll
        for (int j = 0; j < 8; j++) {
            uint4 b = bp[j * 32];
            mma16816(acc[j], Ah, b.x, b.y);
            mma16816(acc[j], Ah, b.z, b.w);
            mma16816(acc[j], Al, b.x, b.y);
        }
        __syncthreads();
    }
    float* dst = khalf ? g_C1b : g_C1a;
    int row0 = bl0 + rowc0;
#pragma unroll
    for (int j = 0; j < 8; j++) {
        int col = ch * 64 + j * 8 + q * 2;
        *(float2*)&dst[(size_t)row0 * NH_ + col]       = make_float2(acc[j][0], acc[j][1]);
        *(float2*)&dst[(size_t)(row0 + 8) * NH_ + col] = make_float2(acc[j][2], acc[j][3]);
    }
}

// ---------------- g2: branch GEMM + fused stats + fused epilogue ----------------
// grid 1024, block 256. CTA: 64 rows x 128 cols, K=256 (k-steps 112..127).
__global__ void __launch_bounds__(256, 2) g2_mma(const float* __restrict__ br0,
                                                 const float* __restrict__ br1,
                                                 const float* __restrict__ br2,
                                                 const float* __restrict__ br3,
                                                 const float* __restrict__ b1,
                                                 const float* __restrict__ W2,
                                                 const float* __restrict__ b2v,
                                                 const float* __restrict__ epsf,
                                                 const float* __restrict__ temp,
                                                 float* __restrict__ out) {
    __shared__ uint4 sB[2][512];           // 16 KB
    __shared__ float sC1[4 * NH_];         // 2 KB
    __shared__ float sS[12 * NH_];         // 6 KB
    __shared__ float sB1[NH_];
    __shared__ float sW2[NH_ * 4];         // 2 KB
    __shared__ float sST[64 * 12];         // 3 KB
    __shared__ float sLog[64][8];          // 2 KB

    int tid = threadIdx.x, w = tid >> 5, lane = tid & 31;
    int q = lane & 3, r4 = lane >> 2;
    int rgrp = w >> 1, ch = w & 1;
    int th0 = blockIdx.x * 64;
    int rowc0 = rgrp * 16 + r4;
    int grow0 = th0 + rowc0;

    // preload tables
    {
        size_t c0 = (size_t)(th0 >> 4) * NH_;
        for (int i = tid; i < 4 * NH_; i += 256) sC1[i] = g_C1a[c0 + i] + g_C1b[c0 + i];
    }
    for (int i = tid; i < 12 * NH_; i += 256) sS[i] = g_S[i];
    if (tid < NH_) sB1[tid] = b1[tid];
    for (int i = tid; i < NH_ * 4; i += 256) sW2[i] = W2[i];

    float acc[8][4];
#pragma unroll
    for (int j = 0; j < 8; j++)
#pragma unroll
        for (int e = 0; e < 4; e++) acc[j][e] = 0.f;

    stage(sB[0], 112, tid);
    __syncthreads();

#pragma unroll 1
    for (int p = 0; p < 4; p++) {
        const float* bp = (p == 0) ? br0 : (p == 1) ? br1 : (p == 2) ? br2 : br3;
        const float* brs0 = bp + (size_t)grow0 * 64 + q * 2;
        const float* brs1 = brs0 + 8 * 64;
        float sum0 = 0.f, sq0 = 0.f, mx0 = -3.402823466e38f;
        float sum1 = 0.f, sq1 = 0.f, mx1 = -3.402823466e38f;
#pragma unroll
        for (int k2 = 0; k2 < 4; k2++) {
            int kk = p * 4 + k2;
            if (kk + 1 < 16) stage(sB[(kk + 1) & 1], 112 + kk + 1, tid);
            uint32_t Ah[4], Al[4];
            float2 v00, v01, v10, v11;
            build_A(brs0 + k2 * 16, brs1 + k2 * 16, Ah, Al, v00, v01, v10, v11);
            sum0 += v00.x + v00.y + v01.x + v01.y;
            sq0 = fmaf(v00.x, v00.x, fmaf(v00.y, v00.y, fmaf(v01.x, v01.x, fmaf(v01.y, v01.y, sq0))));
            mx0 = fmaxf(mx0, fmaxf(fmaxf(v00.x, v00.y), fmaxf(v01.x, v01.y)));
            sum1 += v10.x + v10.y + v11.x + v11.y;
            sq1 = fmaf(v10.x, v10.x, fmaf(v10.y, v10.y, fmaf(v11.x, v11.x, fmaf(v11.y, v11.y, sq1))));
            mx1 = fmaxf(mx1, fmaxf(fmaxf(v10.x, v10.y), fmaxf(v11.x, v11.y)));
            const uint4* bpp = sB[kk & 1] + ch * 256 + lane;
#pragma unroll
            for (int j = 0; j < 8; j++) {
                uint4 b = bpp[j * 32];
                mma16816(acc[j], Ah, b.x, b.y);
                mma16816(acc[j], Ah, b.z, b.w);
                mma16816(acc[j], Al, b.x, b.y);
            }
            __syncthreads();
        }
        // reduce stats over 4-lane groups (rows shared by q lanes); ch==0 warps write
#pragma unroll
        for (int m = 1; m <= 2; m <<= 1) {
            sum0 += __shfl_xor_sync(0xFFFFFFFFu, sum0, m);
            sq0  += __shfl_xor_sync(0xFFFFFFFFu, sq0,  m);
            mx0   = fmaxf(mx0, __shfl_xor_sync(0xFFFFFFFFu, mx0, m));
            sum1 += __shfl_xor_sync(0xFFFFFFFFu, sum1, m);
            sq1  += __shfl_xor_sync(0xFFFFFFFFu, sq1,  m);
            mx1   = fmaxf(mx1, __shfl_xor_sync(0xFFFFFFFFu, mx1, m));
        }
        if (ch == 0 && q == 0) {
            float* st = sST + rowc0 * 12 + p * 3;
            st[0] = sum0 * (1.0f / 64.0f);
            st[1] = sqrtf(fmaxf(sq0 * (1.0f / 64.0f), 1e-8f));
            st[2] = mx0;
            float* st1 = sST + (rowc0 + 8) * 12 + p * 3;
            st1[0] = sum1 * (1.0f / 64.0f);
            st1[1] = sqrtf(fmaxf(sq1 * (1.0f / 64.0f), 1e-8f));
            st1[2] = mx1;
        }
    }
    __syncthreads();

    // ---- epilogue: rows rowc0 (d0,d1) and rowc0+8 (d2,d3), cols ch*64 + j*8 + q*2 ----
#pragma unroll
    for (int rr = 0; rr < 2; rr++) {
        int rowc = rowc0 + rr * 8;
        int bll = rowc >> 4;
        float stl[12];
#pragma unroll
        for (int s2 = 0; s2 < 12; s2++) stl[s2] = sST[rowc * 12 + s2];
        float pl0 = 0.f, pl1 = 0.f, pl2 = 0.f, pl3 = 0.f;
#pragma unroll
        for (int j = 0; j < 8; j++) {
#pragma unroll
            for (int e = 0; e < 2; e++) {
                int col = ch * 64 + j * 8 + q * 2 + e;
                float z = acc[j][rr * 2 + e] + sC1[bll * NH_ + col] + sB1[col];
#pragma unroll
                for (int s2 = 0; s2 < 12; s2++)
                    z = fmaf(stl[s2], sS[s2 * NH_ + col], z);
                float g = 0.5f * z * (1.0f + erff(z * 0.70710678118654752440f));
                pl0 = fmaf(g, sW2[col * 4 + 0], pl0);
                pl1 = fmaf(g, sW2[col * 4 + 1], pl1);
                pl2 = fmaf(g, sW2[col * 4 + 2], pl2);
                pl3 = fmaf(g, sW2[col * 4 + 3], pl3);
            }
        }
#pragma unroll
        for (int m = 1; m <= 2; m <<= 1) {
            pl0 += __shfl_xor_sync(0xFFFFFFFFu, pl0, m);
            pl1 += __shfl_xor_sync(0xFFFFFFFFu, pl1, m);
            pl2 += __shfl_xor_sync(0xFFFFFFFFu, pl2, m);
            pl3 += __shfl_xor_sync(0xFFFFFFFFu, pl3, m);
        }
        if (q == 0) {
            sLog[rowc][ch * 4 + 0] = pl0;
            sLog[rowc][ch * 4 + 1] = pl1;
            sLog[rowc][ch * 4 + 2] = pl2;
            sLog[rowc][ch * 4 + 3] = pl3;
        }
    }
    __syncthreads();

    if (tid < 64) {
        int th = th0 + tid;
        int h = th & (H_ - 1);
        float l0 = sLog[tid][0] + sLog[tid][4] + b2v[0];
        float l1 = sLog[tid][1] + sLog[tid][5] + b2v[1];
        float l2 = sLog[tid][2] + sLog[tid][6] + b2v[2];
        float l3 = sLog[tid][3] + sLog[tid][7] + b2v[3];
        float t = fminf(fmaxf(temp[h], 0.2f), 10.0f);
        float inv_t = 1.0f / t;
        float mx = fmaxf(fmaxf(l0, l1), fmaxf(l2, l3));
        float e0 = expf((l0 - mx) * inv_t);
        float e1 = expf((l1 - mx) * inv_t);
        float e2 = expf((l2 - mx) * inv_t);
        float e3 = expf((l3 - mx) * inv_t);
        float inv = 1.0f / (e0 + e1 + e2 + e3);
        float w0 = e0 * inv, w1 = e1 * inv, w2 = e2 * inv, w3 = e3 * inv;
        float f0 = fminf(fmaxf(epsf[h * 4 + 0], 1e-7f), 0.1f);
        float f1 = fminf(fmaxf(epsf[h * 4 + 1], 1e-7f), 0.1f);
        float f2 = fminf(fmaxf(epsf[h * 4 + 2], 1e-7f), 0.1f);
        float f3 = fminf(fmaxf(epsf[h * 4 + 3], 1e-7f), 0.1f);
        w0 = fmaxf(w0, f0); w1 = fmaxf(w1, f1); w2 = fmaxf(w2, f2); w3 = fmaxf(w3, f3);
        float inv2 = 1.0f / (w0 + w1 + w2 + w3);
        ((float4*)out)[th] = make_float4(w0 * inv2, w1 * inv2, w2 * inv2, w3 * inv2);
    }
}

// ---------------- launch ----------------
extern "C" void kernel_launch(void* const* d_in, const int* in_sizes, int n_in,
                              void* d_out, int out_size) {
    const float* hidden = (const float*)d_in[0];
    const float* br0    = (const float*)d_in[1];
    const float* br1    = (const float*)d_in[2];
    const float* br2    = (const float*)d_in[3];
    const float* br3    = (const float*)d_in[4];
    const float* W1     = (const float*)d_in[5];
    const float* b1     = (const float*)d_in[6];
    const float* W2     = (const float*)d_in[7];
    const float* b2v    = (const float*)d_in[8];
    const float* epsf   = (const float*)d_in[9];
    const float* temp   = (const float*)d_in[10];
    float* out = (float*)d_out;

    prep_S_kernel<<<12, 128>>>(W1);
    prep_pack_kernel<<<256, 256>>>(W1);
    g1_mma<<<dim3(64, 2), 256>>>(hidden);
    g2_mma<<<1024, 256>>>(br0, br1, br2, br3, b1, W2, b2v, epsf, temp, out);
}

// round 10
// speedup vs baseline: 3.5316x; 1.2217x over previous
#include <cuda_runtime.h>
#include <cuda_bf16.h>
#include <math.h>
#include <stdint.h>

#define H_   16
#define HID_ 1024
#define BL_  4096      /* B*L   */
#define TH_  65536     /* B*L*H */
#define NH_  128       /* gate hidden = 2*D */
#define NRB  4096      /* 16-row blocks of token-heads */

// ---------------- device scratch (no allocations) ----------------
// B packed in m16n8k16 fragment order: [ks][n][q] -> uint4 (b0h, b1h, b0l, b1l)
__device__ uint4 g_Bpk[128 * 512];              // 1 MB   (128 ksteps over full K=2048)
// A (branches) packed per 16-row block rb, local kstep ks (0..15), lane -> uint4 frags
__device__ uint4 g_Ahi[(size_t)NRB * 16 * 32];  // 32 MB
__device__ uint4 g_Alo[(size_t)NRB * 16 * 32];  // 32 MB
__device__ float g_S[12 * NH_];                 // stat-block column sums
__device__ float g_C1p[4][BL_ * NH_];           // hidden@W1 k-quarter partials (8 MB)
__device__ float g_stats[TH_ * 12];             // per token-head stats (3 MB)

// ---------------- helpers ----------------
__device__ __forceinline__ uint32_t packbf2(float x, float y) {
    __nv_bfloat162 t = __floats2bfloat162_rn(x, y);
    return *(uint32_t*)&t;
}
__device__ __forceinline__ void split2(float x, float y, uint32_t& hi, uint32_t& lo) {
    __nv_bfloat16 hx = __float2bfloat16_rn(x);
    __nv_bfloat16 hy = __float2bfloat16_rn(y);
    __nv_bfloat162 hh = __halves2bfloat162(hx, hy);
    hi = *(uint32_t*)&hh;
    lo = packbf2(x - __bfloat162float(hx), y - __bfloat162float(hy));
}
__device__ __forceinline__ void mma16816(float* d, const uint32_t* a, uint32_t b0, uint32_t b1) {
    asm volatile(
        "mma.sync.aligned.m16n8k16.row.col.f32.bf16.bf16.f32 "
        "{%0,%1,%2,%3}, {%4,%5,%6,%7}, {%8,%9}, {%0,%1,%2,%3};"
        : "+f"(d[0]), "+f"(d[1]), "+f"(d[2]), "+f"(d[3])
        : "r"(a[0]), "r"(a[1]), "r"(a[2]), "r"(a[3]), "r"(b0), "r"(b1));
}

// ---------------- prep: stat-block column sums ----------------
__global__ void prep_S_kernel(const float* __restrict__ W1) {
    int s = blockIdx.x, o = threadIdx.x;
    const float* base = W1 + (size_t)(HID_ + s * 64) * NH_ + o;
    float acc = 0.f;
#pragma unroll
    for (int d = 0; d < 64; d++) acc += base[d * NH_];
    g_S[s * NH_ + o] = acc;
}

// ---------------- prep: pack W1 (all 2048 k rows) into fragment order ----------------
__global__ void prep_packB(const float* __restrict__ W1) {
    int t = blockIdx.x * 256 + threadIdx.x;   // 65536
    int q = t & 3, n = (t >> 2) & 127, ks = t >> 9;
    int k0 = ks * 16 + q * 2;
    float a0 = W1[(size_t)k0 * NH_ + n];
    float a1 = W1[(size_t)(k0 + 1) * NH_ + n];
    float a8 = W1[(size_t)(k0 + 8) * NH_ + n];
    float a9 = W1[(size_t)(k0 + 9) * NH_ + n];
    uint32_t h01, l01, h89, l89;
    split2(a0, a1, h01, l01);
    split2(a8, a9, h89, l89);
    g_Bpk[t] = make_uint4(h01, h89, l01, l89);
}

// ---------------- prep: pack branches into A-fragment order + fused stats ----------------
// warp task = (rb, branch p). 16384 warps -> grid 2048 x 256.
__global__ void __launch_bounds__(256) prep_packA(const float* __restrict__ br0,
                                                  const float* __restrict__ br1,
                                                  const float* __restrict__ br2,
                                                  const float* __restrict__ br3) {
    int tid = threadIdx.x, w = tid >> 5, lane = tid & 31;
    int task = blockIdx.x * 8 + w;
    int rb = task >> 2, p = task & 3;
    int q = lane & 3, r4 = lane >> 2;
    const float* bp = (p == 0) ? br0 : (p == 1) ? br1 : (p == 2) ? br2 : br3;
    int th0 = rb * 16;
    const float* rp0 = bp + (size_t)(th0 + r4) * 64 + q * 2;
    const float* rp1 = rp0 + 8 * 64;

    float sum0 = 0.f, sq0 = 0.f, mx0 = -3.402823466e38f;
    float sum1 = 0.f, sq1 = 0.f, mx1 = -3.402823466e38f;
#pragma unroll
    for (int k4 = 0; k4 < 4; k4++) {
        float2 v00 = *(const float2*)(rp0 + k4 * 16);
        float2 v01 = *(const float2*)(rp0 + k4 * 16 + 8);
        float2 v10 = *(const float2*)(rp1 + k4 * 16);
        float2 v11 = *(const float2*)(rp1 + k4 * 16 + 8);
        uint4 hi, lo;
        split2(v00.x, v00.y, hi.x, lo.x);
        split2(v10.x, v10.y, hi.y, lo.y);
        split2(v01.x, v01.y, hi.z, lo.z);
        split2(v11.x, v11.y, hi.w, lo.w);
        size_t idx = ((size_t)rb * 16 + p * 4 + k4) * 32 + lane;
        g_Ahi[idx] = hi;
        g_Alo[idx] = lo;
        sum0 += v00.x + v00.y + v01.x + v01.y;
        sq0 = fmaf(v00.x, v00.x, fmaf(v00.y, v00.y, fmaf(v01.x, v01.x, fmaf(v01.y, v01.y, sq0))));
        mx0 = fmaxf(mx0, fmaxf(fmaxf(v00.x, v00.y), fmaxf(v01.x, v01.y)));
        sum1 += v10.x + v10.y + v11.x + v11.y;
        sq1 = fmaf(v10.x, v10.x, fmaf(v10.y, v10.y, fmaf(v11.x, v11.x, fmaf(v11.y, v11.y, sq1))));
        mx1 = fmaxf(mx1, fmaxf(fmaxf(v10.x, v10.y), fmaxf(v11.x, v11.y)));
    }
#pragma unroll
    for (int m = 1; m <= 2; m <<= 1) {
        sum0 += __shfl_xor_sync(0xFFFFFFFFu, sum0, m);
        sq0  += __shfl_xor_sync(0xFFFFFFFFu, sq0,  m);
        mx0   = fmaxf(mx0, __shfl_xor_sync(0xFFFFFFFFu, mx0, m));
        sum1 += __shfl_xor_sync(0xFFFFFFFFu, sum1, m);
        sq1  += __shfl_xor_sync(0xFFFFFFFFu, sq1,  m);
        mx1   = fmaxf(mx1, __shfl_xor_sync(0xFFFFFFFFu, mx1, m));
    }
    if (q == 0) {
        float* st = g_stats + (size_t)(th0 + r4) * 12 + p * 3;
        st[0] = sum0 * (1.0f / 64.0f);
        st[1] = sqrtf(fmaxf(sq0 * (1.0f / 64.0f), 1e-8f));
        st[2] = mx0;
        float* st1 = g_stats + (size_t)(th0 + r4 + 8) * 12 + p * 3;
        st1[0] = sum1 * (1.0f / 64.0f);
        st1[1] = sqrtf(fmaxf(sq1 * (1.0f / 64.0f), 1e-8f));
        st1[2] = mx1;
    }
}

// ---------------- g1: C1 partials, sync-free mainloop ----------------
// grid (64, 4), block 256. CTA: 64 rows x 128 cols, K=256 (k-quarter).
// warp w: rowgroup rg = w>>2 (32 rows), colquarter cq = w&3 (32 cols).
__global__ void __launch_bounds__(256, 2) g1_mma(const float* __restrict__ hidden) {
    int tid = threadIdx.x, w = tid >> 5, lane = tid & 31;
    int q = lane & 3, r4 = lane >> 2;
    int rg = w >> 2, cq = w & 3;
    int bl0 = blockIdx.x * 64;
    int kq = blockIdx.y;

    float acc[2][4][4] = {};
    const float* rbase[2][2];
#pragma unroll
    for (int i = 0; i < 2; i++) {
        rbase[i][0] = hidden + (size_t)(bl0 + rg * 32 + i * 16 + r4) * HID_ + kq * 256 + q * 2;
        rbase[i][1] = rbase[i][0] + 8 * HID_;
    }

#pragma unroll 2
    for (int kl = 0; kl < 16; kl++) {
        uint32_t Ah[2][4], Al[2][4];
#pragma unroll
        for (int i = 0; i < 2; i++) {
            float2 v00 = *(const float2*)(rbase[i][0] + kl * 16);
            float2 v01 = *(const float2*)(rbase[i][0] + kl * 16 + 8);
            float2 v10 = *(const float2*)(rbase[i][1] + kl * 16);
            float2 v11 = *(const float2*)(rbase[i][1] + kl * 16 + 8);
            split2(v00.x, v00.y, Ah[i][0], Al[i][0]);
            split2(v10.x, v10.y, Ah[i][1], Al[i][1]);
            split2(v01.x, v01.y, Ah[i][2], Al[i][2]);
            split2(v11.x, v11.y, Ah[i][3], Al[i][3]);
        }
        const uint4* bq = g_Bpk + (size_t)(kq * 16 + kl) * 512 + cq * 128 + lane;
#pragma unroll
        for (int j = 0; j < 4; j++) {
            uint4 b = bq[j * 32];
#pragma unroll
            for (int i = 0; i < 2; i++) {
                mma16816(acc[i][j], Ah[i], b.x, b.y);
                mma16816(acc[i][j], Ah[i], b.z, b.w);
                mma16816(acc[i][j], Al[i], b.x, b.y);
            }
        }
    }
    float* dst = g_C1p[kq];
#pragma unroll
    for (int i = 0; i < 2; i++) {
        int row0 = bl0 + rg * 32 + i * 16 + r4;
#pragma unroll
        for (int j = 0; j < 4; j++) {
            int col = cq * 32 + j * 8 + q * 2;
            *(float2*)&dst[(size_t)row0 * NH_ + col]       = make_float2(acc[i][j][0], acc[i][j][1]);
            *(float2*)&dst[(size_t)(row0 + 8) * NH_ + col] = make_float2(acc[i][j][2], acc[i][j][3]);
        }
    }
}

// ---------------- g2: lean branch GEMM + fused epilogue ----------------
// grid 1024, block 256. CTA: 64 rows x 128 cols. No smem staging, no mainloop syncs.
__global__ void __launch_bounds__(256, 2) g2_mma(const float* __restrict__ b1,
                                                 const float* __restrict__ W2,
                                                 const float* __restrict__ b2v,
                                                 const float* __restrict__ epsf,
                                                 const float* __restrict__ temp,
                                                 float* __restrict__ out) {
    __shared__ float sC1[4 * NH_];      // 2 KB
    __shared__ float sS[12 * NH_];      // 6 KB
    __shared__ float sB1[NH_];
    __shared__ float sW2[NH_ * 4];      // 2 KB
    __shared__ float sST[64 * 12];      // 3 KB
    __shared__ float sLog[64][16];      // 4 KB

    int tid = threadIdx.x, w = tid >> 5, lane = tid & 31;
    int q = lane & 3, r4 = lane >> 2;
    int rg = w >> 2, cq = w & 3;
    int th0 = blockIdx.x * 64;

    // preload tables (only sync point before epilogue merge)
    {
        size_t c0 = (size_t)(th0 >> 4) * NH_;
        for (int i = tid; i < 4 * NH_; i += 256)
            sC1[i] = g_C1p[0][c0 + i] + g_C1p[1][c0 + i] + g_C1p[2][c0 + i] + g_C1p[3][c0 + i];
    }
    for (int i = tid; i < 12 * NH_; i += 256) sS[i] = g_S[i];
    if (tid < NH_) sB1[tid] = b1[tid];
    for (int i = tid; i < NH_ * 4; i += 256) sW2[i] = W2[i];
    for (int i = tid; i < 64 * 12; i += 256) sST[i] = g_stats[(size_t)th0 * 12 + i];

    float acc[2][4][4] = {};
    size_t rb0 = (size_t)(blockIdx.x * 4 + rg * 2);

#pragma unroll 2
    for (int kl = 0; kl < 16; kl++) {
        uint4 ah0 = g_Ahi[(rb0 * 16 + kl) * 32 + lane];
        uint4 al0 = g_Alo[(rb0 * 16 + kl) * 32 + lane];
        uint4 ah1 = g_Ahi[((rb0 + 1) * 16 + kl) * 32 + lane];
        uint4 al1 = g_Alo[((rb0 + 1) * 16 + kl) * 32 + lane];
        const uint4* bq = g_Bpk + (size_t)(112 + kl) * 512 + cq * 128 + lane;
#pragma unroll
        for (int j = 0; j < 4; j++) {
            uint4 b = bq[j * 32];
            mma16816(acc[0][j], &ah0.x, b.x, b.y);
            mma16816(acc[0][j], &ah0.x, b.z, b.w);
            mma16816(acc[0][j], &al0.x, b.x, b.y);
            mma16816(acc[1][j], &ah1.x, b.x, b.y);
            mma16816(acc[1][j], &ah1.x, b.z, b.w);
            mma16816(acc[1][j], &al1.x, b.x, b.y);
        }
    }
    __syncthreads();   // tables ready (also separates any late preload)

    // ---- epilogue: 4 row-slots per thread (i x d-pair), 8 cols each ----
    float pl[4][4];
#pragma unroll
    for (int s = 0; s < 4; s++)
#pragma unroll
        for (int c = 0; c < 4; c++) pl[s][c] = 0.f;

#pragma unroll
    for (int i = 0; i < 2; i++) {
#pragma unroll
        for (int rr = 0; rr < 2; rr++) {
            int rowc = rg * 32 + i * 16 + r4 + rr * 8;
            int bll = rowc >> 4;
            int slot = i * 2 + rr;
            const float* stl = sST + rowc * 12;
#pragma unroll
            for (int j = 0; j < 4; j++) {
#pragma unroll
                for (int e = 0; e < 2; e++) {
                    int col = cq * 32 + j * 8 + q * 2 + e;
                    float z = acc[i][j][rr * 2 + e] + sC1[bll * NH_ + col] + sB1[col];
#pragma unroll
                    for (int s2 = 0; s2 < 12; s2++)
                        z = fmaf(stl[s2], sS[s2 * NH_ + col], z);
                    float g = 0.5f * z * (1.0f + erff(z * 0.70710678118654752440f));
                    pl[slot][0] = fmaf(g, sW2[col * 4 + 0], pl[slot][0]);
                    pl[slot][1] = fmaf(g, sW2[col * 4 + 1], pl[slot][1]);
                    pl[slot][2] = fmaf(g, sW2[col * 4 + 2], pl[slot][2]);
                    pl[slot][3] = fmaf(g, sW2[col * 4 + 3], pl[slot][3]);
                }
            }
        }
    }
#pragma unroll
    for (int m = 1; m <= 2; m <<= 1)
#pragma unroll
        for (int s = 0; s < 4; s++)
#pragma unroll
            for (int c = 0; c < 4; c++)
                pl[s][c] += __shfl_xor_sync(0xFFFFFFFFu, pl[s][c], m);
    if (q == 0) {
#pragma unroll
        for (int i = 0; i < 2; i++)
#pragma unroll
            for (int rr = 0; rr < 2; rr++) {
                int rowc = rg * 32 + i * 16 + r4 + rr * 8;
                int slot = i * 2 + rr;
#pragma unroll
                for (int c = 0; c < 4; c++)
                    sLog[rowc][cq * 4 + c] = pl[slot][c];
            }
    }
    __syncthreads();

    if (tid < 64) {
        int th = th0 + tid;
        int h = th & (H_ - 1);
        float l0 = sLog[tid][0] + sLog[tid][4] + sLog[tid][8]  + sLog[tid][12] + b2v[0];
        float l1 = sLog[tid][1] + sLog[tid][5] + sLog[tid][9]  + sLog[tid][13] + b2v[1];
        float l2 = sLog[tid][2] + sLog[tid][6] + sLog[tid][10] + sLog[tid][14] + b2v[2];
        float l3 = sLog[tid][3] + sLog[tid][7] + sLog[tid][11] + sLog[tid][15] + b2v[3];
        float t = fminf(fmaxf(temp[h], 0.2f), 10.0f);
        float inv_t = 1.0f / t;
        float mx = fmaxf(fmaxf(l0, l1), fmaxf(l2, l3));
        float e0 = expf((l0 - mx) * inv_t);
        float e1 = expf((l1 - mx) * inv_t);
        float e2 = expf((l2 - mx) * inv_t);
        float e3 = expf((l3 - mx) * inv_t);
        float inv = 1.0f / (e0 + e1 + e2 + e3);
        float w0 = e0 * inv, w1 = e1 * inv, w2 = e2 * inv, w3 = e3 * inv;
        float f0 = fminf(fmaxf(epsf[h * 4 + 0], 1e-7f), 0.1f);
        float f1 = fminf(fmaxf(epsf[h * 4 + 1], 1e-7f), 0.1f);
        float f2 = fminf(fmaxf(epsf[h * 4 + 2], 1e-7f), 0.1f);
        float f3 = fminf(fmaxf(epsf[h * 4 + 3], 1e-7f), 0.1f);
        w0 = fmaxf(w0, f0); w1 = fmaxf(w1, f1); w2 = fmaxf(w2, f2); w3 = fmaxf(w3, f3);
        float inv2 = 1.0f / (w0 + w1 + w2 + w3);
        ((float4*)out)[th] = make_float4(w0 * inv2, w1 * inv2, w2 * inv2, w3 * inv2);
    }
}

// ---------------- launch ----------------
extern "C" void kernel_launch(void* const* d_in, const int* in_sizes, int n_in,
                              void* d_out, int out_size) {
    const float* hidden = (const float*)d_in[0];
    const float* br0    = (const float*)d_in[1];
    const float* br1    = (const float*)d_in[2];
    const float* br2    = (const float*)d_in[3];
    const float* br3    = (const float*)d_in[4];
    const float* W1     = (const float*)d_in[5];
    const float* b1     = (const float*)d_in[6];
    const float* W2     = (const float*)d_in[7];
    const float* b2v    = (const float*)d_in[8];
    const float* epsf   = (const float*)d_in[9];
    const float* temp   = (const float*)d_in[10];
    float* out = (float*)d_out;

    prep_S_kernel<<<12, 128>>>(W1);
    prep_packB<<<256, 256>>>(W1);
    prep_packA<<<2048, 256>>>(br0, br1, br2, br3);
    g1_mma<<<dim3(64, 4), 256>>>(hidden);
    g2_mma<<<1024, 256>>>(b1, W2, b2v, epsf, temp, out);
}

// round 11
// speedup vs baseline: 4.2201x; 1.1950x over previous
#include <cuda_runtime.h>
#include <cuda_bf16.h>
#include <math.h>
#include <stdint.h>

#define H_   16
#define HID_ 1024
#define BL_  4096      /* B*L   */
#define TH_  65536     /* B*L*H */
#define NH_  128       /* gate hidden = 2*D */

// ---------------- device scratch (no allocations) ----------------
// B packed in m16n8k16 fragment order: [ks][n][q] -> uint4 (b0h, b1h, b0l, b1l)
__device__ uint4 g_Bpk[128 * 512];              // 1 MB (128 ksteps over K=2048)
__device__ float g_S[12 * NH_];                 // stat-block column sums
__device__ float g_C1p[4][BL_ * NH_];           // hidden@W1 k-quarter partials (8 MB)

// ---------------- helpers ----------------
__device__ __forceinline__ uint32_t packbf2(float x, float y) {
    __nv_bfloat162 t = __floats2bfloat162_rn(x, y);
    return *(uint32_t*)&t;
}
__device__ __forceinline__ void split2(float x, float y, uint32_t& hi, uint32_t& lo) {
    __nv_bfloat16 hx = __float2bfloat16_rn(x);
    __nv_bfloat16 hy = __float2bfloat16_rn(y);
    __nv_bfloat162 hh = __halves2bfloat162(hx, hy);
    hi = *(uint32_t*)&hh;
    lo = packbf2(x - __bfloat162float(hx), y - __bfloat162float(hy));
}
__device__ __forceinline__ void mma16816(float* d, const uint32_t* a, uint32_t b0, uint32_t b1) {
    asm volatile(
        "mma.sync.aligned.m16n8k16.row.col.f32.bf16.bf16.f32 "
        "{%0,%1,%2,%3}, {%4,%5,%6,%7}, {%8,%9}, {%0,%1,%2,%3};"
        : "+f"(d[0]), "+f"(d[1]), "+f"(d[2]), "+f"(d[3])
        : "r"(a[0]), "r"(a[1]), "r"(a[2]), "r"(a[3]), "r"(b0), "r"(b1));
}

// ---------------- prep (merged): packB (blocks 0..255) + S sums (blocks 256..267) ----------------
__global__ void prep_kernel(const float* __restrict__ W1) {
    int bid = blockIdx.x, tid = threadIdx.x;
    if (bid < 256) {
        int t = bid * 256 + tid;   // 65536
        int q = t & 3, n = (t >> 2) & 127, ks = t >> 9;
        int k0 = ks * 16 + q * 2;
        float a0 = W1[(size_t)k0 * NH_ + n];
        float a1 = W1[(size_t)(k0 + 1) * NH_ + n];
        float a8 = W1[(size_t)(k0 + 8) * NH_ + n];
        float a9 = W1[(size_t)(k0 + 9) * NH_ + n];
        uint32_t h01, l01, h89, l89;
        split2(a0, a1, h01, l01);
        split2(a8, a9, h89, l89);
        g_Bpk[t] = make_uint4(h01, h89, l01, l89);
    } else if (tid < 128) {
        int s = bid - 256, o = tid;
        const float* base = W1 + (size_t)(HID_ + s * 64) * NH_ + o;
        float acc = 0.f;
#pragma unroll
        for (int d = 0; d < 64; d++) acc += base[d * NH_];
        g_S[s * NH_ + o] = acc;
    }
}

// ---------------- g1: C1 partials, sync-free mainloop with A prefetch ----------------
// grid (64, 4), block 256. CTA: 64 rows x 128 cols, K=256 (k-quarter).
__global__ void __launch_bounds__(256, 2) g1_mma(const float* __restrict__ hidden) {
    int tid = threadIdx.x, w = tid >> 5, lane = tid & 31;
    int q = lane & 3, r4 = lane >> 2;
    int rg = w >> 2, cq = w & 3;
    int bl0 = blockIdx.x * 64;
    int kq = blockIdx.y;

    float acc[2][4][4] = {};
    const float* rbase[2][2];
#pragma unroll
    for (int i = 0; i < 2; i++) {
        rbase[i][0] = hidden + (size_t)(bl0 + rg * 32 + i * 16 + r4) * HID_ + kq * 256 + q * 2;
        rbase[i][1] = rbase[i][0] + 8 * HID_;
    }

    float2 cv[2][4];
#pragma unroll
    for (int i = 0; i < 2; i++) {
        cv[i][0] = *(const float2*)(rbase[i][0]);
        cv[i][1] = *(const float2*)(rbase[i][0] + 8);
        cv[i][2] = *(const float2*)(rbase[i][1]);
        cv[i][3] = *(const float2*)(rbase[i][1] + 8);
    }

#pragma unroll 2
    for (int kl = 0; kl < 16; kl++) {
        float2 nv[2][4];
        if (kl < 15) {
#pragma unroll
            for (int i = 0; i < 2; i++) {
                nv[i][0] = *(const float2*)(rbase[i][0] + (kl + 1) * 16);
                nv[i][1] = *(const float2*)(rbase[i][0] + (kl + 1) * 16 + 8);
                nv[i][2] = *(const float2*)(rbase[i][1] + (kl + 1) * 16);
                nv[i][3] = *(const float2*)(rbase[i][1] + (kl + 1) * 16 + 8);
            }
        }
        uint32_t Ah[2][4], Al[2][4];
#pragma unroll
        for (int i = 0; i < 2; i++) {
            split2(cv[i][0].x, cv[i][0].y, Ah[i][0], Al[i][0]);
            split2(cv[i][2].x, cv[i][2].y, Ah[i][1], Al[i][1]);
            split2(cv[i][1].x, cv[i][1].y, Ah[i][2], Al[i][2]);
            split2(cv[i][3].x, cv[i][3].y, Ah[i][3], Al[i][3]);
        }
        const uint4* bq = g_Bpk + (size_t)(kq * 16 + kl) * 512 + cq * 128 + lane;
#pragma unroll
        for (int j = 0; j < 4; j++) {
            uint4 b = bq[j * 32];
#pragma unroll
            for (int i = 0; i < 2; i++) {
                mma16816(acc[i][j], Ah[i], b.x, b.y);
                mma16816(acc[i][j], Ah[i], b.z, b.w);
                mma16816(acc[i][j], Al[i], b.x, b.y);
            }
        }
#pragma unroll
        for (int i = 0; i < 2; i++)
#pragma unroll
            for (int e = 0; e < 4; e++) cv[i][e] = nv[i][e];
    }
    float* dst = g_C1p[kq];
#pragma unroll
    for (int i = 0; i < 2; i++) {
        int row0 = bl0 + rg * 32 + i * 16 + r4;
#pragma unroll
        for (int j = 0; j < 4; j++) {
            int col = cq * 32 + j * 8 + q * 2;
            *(float2*)&dst[(size_t)row0 * NH_ + col]       = make_float2(acc[i][j][0], acc[i][j][1]);
            *(float2*)&dst[(size_t)(row0 + 8) * NH_ + col] = make_float2(acc[i][j][2], acc[i][j][3]);
        }
    }
}

// ---------------- g2: branch GEMM, fused convert (via smem frags) + stats + epilogue ----------------
// grid 1024, block 256. CTA: 64 rows x 128 cols, K=256.
// Convert phase per branch: warp w builds fragment sets (b = w&3, kl = w>>2 and w>>2 + 2).
__global__ void __launch_bounds__(256, 2) g2_mma(const float* __restrict__ br0,
                                                 const float* __restrict__ br1,
                                                 const float* __restrict__ br2,
                                                 const float* __restrict__ br3,
                                                 const float* __restrict__ b1,
                                                 const float* __restrict__ W2,
                                                 const float* __restrict__ b2v,
                                                 const float* __restrict__ epsf,
                                                 const float* __restrict__ temp,
                                                 float* __restrict__ out) {
    __shared__ uint4 sAh[4][4][32];     // 8 KB  [block][kstep][lane]
    __shared__ uint4 sAl[4][4][32];     // 8 KB
    __shared__ float sC1[4 * NH_];      // 2 KB
    __shared__ float sS[12 * NH_];      // 6 KB
    __shared__ float sB1[NH_];
    __shared__ float sW2[NH_ * 4];      // 2 KB
    __shared__ float sSTp[2][64][12];   // 6 KB  raw per-k-half stat partials
    __shared__ float sST[64 * 12];      // 3 KB
    __shared__ float sLog[64][16];      // 4 KB

    int tid = threadIdx.x, w = tid >> 5, lane = tid & 31;
    int q = lane & 3, r4 = lane >> 2;
    int rg = w >> 2, cq = w & 3;
    int th0 = blockIdx.x * 64;
    int cb = w & 3;         // convert: this warp's 16-row block
    int ckl = w >> 2;       // convert: base kstep (handles ckl and ckl+2)

    // preload tables
    {
        size_t c0 = (size_t)(th0 >> 4) * NH_;
        for (int i = tid; i < 4 * NH_; i += 256)
            sC1[i] = g_C1p[0][c0 + i] + g_C1p[1][c0 + i] + g_C1p[2][c0 + i] + g_C1p[3][c0 + i];
    }
    for (int i = tid; i < 12 * NH_; i += 256) sS[i] = g_S[i];
    if (tid < NH_) sB1[tid] = b1[tid];
    for (int i = tid; i < NH_ * 4; i += 256) sW2[i] = W2[i];

    float acc[2][4][4] = {};

#pragma unroll 1
    for (int p = 0; p < 4; p++) {
        const float* bp = (p == 0) ? br0 : (p == 1) ? br1 : (p == 2) ? br2 : br3;
        // ---- convert phase ----
        float sum0 = 0.f, sq0 = 0.f, mx0 = -3.402823466e38f;
        float sum1 = 0.f, sq1 = 0.f, mx1 = -3.402823466e38f;
#pragma unroll
        for (int u = 0; u < 2; u++) {
            int kl = ckl + u * 2;
            const float* rp0 = bp + (size_t)(th0 + cb * 16 + r4) * 64 + kl * 16 + q * 2;
            const float* rp1 = rp0 + 8 * 64;
            float2 v00 = *(const float2*)(rp0);
            float2 v01 = *(const float2*)(rp0 + 8);
            float2 v10 = *(const float2*)(rp1);
            float2 v11 = *(const float2*)(rp1 + 8);
            uint4 hi, lo;
            split2(v00.x, v00.y, hi.x, lo.x);
            split2(v10.x, v10.y, hi.y, lo.y);
            split2(v01.x, v01.y, hi.z, lo.z);
            split2(v11.x, v11.y, hi.w, lo.w);
            sAh[cb][kl][lane] = hi;
            sAl[cb][kl][lane] = lo;
            sum0 += v00.x + v00.y + v01.x + v01.y;
            sq0 = fmaf(v00.x, v00.x, fmaf(v00.y, v00.y, fmaf(v01.x, v01.x, fmaf(v01.y, v01.y, sq0))));
            mx0 = fmaxf(mx0, fmaxf(fmaxf(v00.x, v00.y), fmaxf(v01.x, v01.y)));
            sum1 += v10.x + v10.y + v11.x + v11.y;
            sq1 = fmaf(v10.x, v10.x, fmaf(v10.y, v10.y, fmaf(v11.x, v11.x, fmaf(v11.y, v11.y, sq1))));
            mx1 = fmaxf(mx1, fmaxf(fmaxf(v10.x, v10.y), fmaxf(v11.x, v11.y)));
        }
#pragma unroll
        for (int m = 1; m <= 2; m <<= 1) {
            sum0 += __shfl_xor_sync(0xFFFFFFFFu, sum0, m);
            sq0  += __shfl_xor_sync(0xFFFFFFFFu, sq0,  m);
            mx0   = fmaxf(mx0, __shfl_xor_sync(0xFFFFFFFFu, mx0, m));
            sum1 += __shfl_xor_sync(0xFFFFFFFFu, sum1, m);
            sq1  += __shfl_xor_sync(0xFFFFFFFFu, sq1,  m);
            mx1   = fmaxf(mx1, __shfl_xor_sync(0xFFFFFFFFu, mx1, m));
        }
        if (q == 0) {
            sSTp[ckl][cb * 16 + r4][p * 3 + 0] = sum0;
            sSTp[ckl][cb * 16 + r4][p * 3 + 1] = sq0;
            sSTp[ckl][cb * 16 + r4][p * 3 + 2] = mx0;
            sSTp[ckl][cb * 16 + r4 + 8][p * 3 + 0] = sum1;
            sSTp[ckl][cb * 16 + r4 + 8][p * 3 + 1] = sq1;
            sSTp[ckl][cb * 16 + r4 + 8][p * 3 + 2] = mx1;
        }
        __syncthreads();
        // ---- mma phase ----
#pragma unroll
        for (int kl = 0; kl < 4; kl++) {
            uint4 ah0 = sAh[rg * 2][kl][lane];
            uint4 al0 = sAl[rg * 2][kl][lane];
            uint4 ah1 = sAh[rg * 2 + 1][kl][lane];
            uint4 al1 = sAl[rg * 2 + 1][kl][lane];
            const uint4* bq = g_Bpk + (size_t)(112 + p * 4 + kl) * 512 + cq * 128 + lane;
#pragma unroll
            for (int j = 0; j < 4; j++) {
                uint4 b = bq[j * 32];
                mma16816(acc[0][j], &ah0.x, b.x, b.y);
                mma16816(acc[0][j], &ah0.x, b.z, b.w);
                mma16816(acc[0][j], &al0.x, b.x, b.y);
                mma16816(acc[1][j], &ah1.x, b.x, b.y);
                mma16816(acc[1][j], &ah1.x, b.z, b.w);
                mma16816(acc[1][j], &al1.x, b.x, b.y);
            }
        }
        __syncthreads();
    }

    // ---- finalize stats ----
    if (tid < 64) {
#pragma unroll
        for (int p = 0; p < 4; p++) {
            float sa = sSTp[0][tid][p * 3 + 0] + sSTp[1][tid][p * 3 + 0];
            float sv = sSTp[0][tid][p * 3 + 1] + sSTp[1][tid][p * 3 + 1];
            float mv = fmaxf(sSTp[0][tid][p * 3 + 2], sSTp[1][tid][p * 3 + 2]);
            sST[tid * 12 + p * 3 + 0] = sa * (1.0f / 64.0f);
            sST[tid * 12 + p * 3 + 1] = sqrtf(fmaxf(sv * (1.0f / 64.0f), 1e-8f));
            sST[tid * 12 + p * 3 + 2] = mv;
        }
    }
    __syncthreads();

    // ---- epilogue ----
    float pl[4][4];
#pragma unroll
    for (int s = 0; s < 4; s++)
#pragma unroll
        for (int c = 0; c < 4; c++) pl[s][c] = 0.f;

#pragma unroll
    for (int i = 0; i < 2; i++) {
#pragma unroll
        for (int rr = 0; rr < 2; rr++) {
            int rowc = rg * 32 + i * 16 + r4 + rr * 8;
            int bll = rowc >> 4;
            int slot = i * 2 + rr;
            const float* stl = sST + rowc * 12;
#pragma unroll
            for (int j = 0; j < 4; j++) {
#pragma unroll
                for (int e = 0; e < 2; e++) {
                    int col = cq * 32 + j * 8 + q * 2 + e;
                    float z = acc[i][j][rr * 2 + e] + sC1[bll * NH_ + col] + sB1[col];
#pragma unroll
                    for (int s2 = 0; s2 < 12; s2++)
                        z = fmaf(stl[s2], sS[s2 * NH_ + col], z);
                    float g = 0.5f * z * (1.0f + erff(z * 0.70710678118654752440f));
                    pl[slot][0] = fmaf(g, sW2[col * 4 + 0], pl[slot][0]);
                    pl[slot][1] = fmaf(g, sW2[col * 4 + 1], pl[slot][1]);
                    pl[slot][2] = fmaf(g, sW2[col * 4 + 2], pl[slot][2]);
                    pl[slot][3] = fmaf(g, sW2[col * 4 + 3], pl[slot][3]);
                }
            }
        }
    }
#pragma unroll
    for (int m = 1; m <= 2; m <<= 1)
#pragma unroll
        for (int s = 0; s < 4; s++)
#pragma unroll
            for (int c = 0; c < 4; c++)
                pl[s][c] += __shfl_xor_sync(0xFFFFFFFFu, pl[s][c], m);
    if (q == 0) {
#pragma unroll
        for (int i = 0; i < 2; i++)
#pragma unroll
            for (int rr = 0; rr < 2; rr++) {
                int rowc = rg * 32 + i * 16 + r4 + rr * 8;
                int slot = i * 2 + rr;
#pragma unroll
                for (int c = 0; c < 4; c++)
                    sLog[rowc][cq * 4 + c] = pl[slot][c];
            }
    }
    __syncthreads();

    if (tid < 64) {
        int th = th0 + tid;
        int h = th & (H_ - 1);
        float l0 = sLog[tid][0] + sLog[tid][4] + sLog[tid][8]  + sLog[tid][12] + b2v[0];
        float l1 = sLog[tid][1] + sLog[tid][5] + sLog[tid][9]  + sLog[tid][13] + b2v[1];
        float l2 = sLog[tid][2] + sLog[tid][6] + sLog[tid][10] + sLog[tid][14] + b2v[2];
        float l3 = sLog[tid][3] + sLog[tid][7] + sLog[tid][11] + sLog[tid][15] + b2v[3];
        float t = fminf(fmaxf(temp[h], 0.2f), 10.0f);
        float inv_t = 1.0f / t;
        float mx = fmaxf(fmaxf(l0, l1), fmaxf(l2, l3));
        float e0 = expf((l0 - mx) * inv_t);
        float e1 = expf((l1 - mx) * inv_t);
        float e2 = expf((l2 - mx) * inv_t);
        float e3 = expf((l3 - mx) * inv_t);
        float inv = 1.0f / (e0 + e1 + e2 + e3);
        float w0 = e0 * inv, w1 = e1 * inv, w2 = e2 * inv, w3 = e3 * inv;
        float f0 = fminf(fmaxf(epsf[h * 4 + 0], 1e-7f), 0.1f);
        float f1 = fminf(fmaxf(epsf[h * 4 + 1], 1e-7f), 0.1f);
        float f2 = fminf(fmaxf(epsf[h * 4 + 2], 1e-7f), 0.1f);
        float f3 = fminf(fmaxf(epsf[h * 4 + 3], 1e-7f), 0.1f);
        w0 = fmaxf(w0, f0); w1 = fmaxf(w1, f1); w2 = fmaxf(w2, f2); w3 = fmaxf(w3, f3);
        float inv2 = 1.0f / (w0 + w1 + w2 + w3);
        ((float4*)out)[th] = make_float4(w0 * inv2, w1 * inv2, w2 * inv2, w3 * inv2);
    }
}

// ---------------- launch ----------------
extern "C" void kernel_launch(void* const* d_in, const int* in_sizes, int n_in,
                              void* d_out, int out_size) {
    const float* hidden = (const float*)d_in[0];
    const float* br0    = (const float*)d_in[1];
    const float* br1    = (const float*)d_in[2];
    const float* br2    = (const float*)d_in[3];
    const float* br3    = (const float*)d_in[4];
    const float* W1     = (const float*)d_in[5];
    const float* b1     = (const float*)d_in[6];
    const float* W2     = (const float*)d_in[7];
    const float* b2v    = (const float*)d_in[8];
    const float* epsf   = (const float*)d_in[9];
    const float* temp   = (const float*)d_in[10];
    float* out = (float*)d_out;

    prep_kernel<<<268, 256>>>(W1);
    g1_mma<<<dim3(64, 4), 256>>>(hidden);
    g2_mma<<<1024, 256>>>(br0, br1, br2, br3, b1, W2, b2v, epsf, temp, out);
}

// round 12
// speedup vs baseline: 5.0435x; 1.1951x over previous
#include <cuda_runtime.h>
#include <cuda_bf16.h>
#include <math.h>
#include <stdint.h>

#define H_   16
#define HID_ 1024
#define BL_  4096      /* B*L   */
#define TH_  65536     /* B*L*H */
#define NH_  128       /* gate hidden = 2*D */

// ---------------- device scratch (no allocations) ----------------
// B packed in m16n8k16 fragment order: [ks][n][q] -> uint4 (b0h, b1h, b0l, b1l)
__device__ uint4 g_Bpk[128 * 512];              // 1 MB (128 ksteps over K=2048)
__device__ float g_S[12 * NH_];                 // stat-block column sums
__device__ float g_C1p[4][BL_ * NH_];           // hidden@W1 k-quarter partials (8 MB)

// ---------------- helpers ----------------
__device__ __forceinline__ uint32_t packbf2(float x, float y) {
    __nv_bfloat162 t = __floats2bfloat162_rn(x, y);
    return *(uint32_t*)&t;
}
__device__ __forceinline__ void split2(float x, float y, uint32_t& hi, uint32_t& lo) {
    __nv_bfloat16 hx = __float2bfloat16_rn(x);
    __nv_bfloat16 hy = __float2bfloat16_rn(y);
    __nv_bfloat162 hh = __halves2bfloat162(hx, hy);
    hi = *(uint32_t*)&hh;
    lo = packbf2(x - __bfloat162float(hx), y - __bfloat162float(hy));
}
__device__ __forceinline__ void mma16816(float* d, const uint32_t* a, uint32_t b0, uint32_t b1) {
    asm volatile(
        "mma.sync.aligned.m16n8k16.row.col.f32.bf16.bf16.f32 "
        "{%0,%1,%2,%3}, {%4,%5,%6,%7}, {%8,%9}, {%0,%1,%2,%3};"
        : "+f"(d[0]), "+f"(d[1]), "+f"(d[2]), "+f"(d[3])
        : "r"(a[0]), "r"(a[1]), "r"(a[2]), "r"(a[3]), "r"(b0), "r"(b1));
}

// ---------------- prep (merged): packB (blocks 0..255) + S sums (blocks 256..267) ----------------
__global__ void prep_kernel(const float* __restrict__ W1) {
    int bid = blockIdx.x, tid = threadIdx.x;
    if (bid < 256) {
        int t = bid * 256 + tid;   // 65536
        int q = t & 3, n = (t >> 2) & 127, ks = t >> 9;
        int k0 = ks * 16 + q * 2;
        float a0 = W1[(size_t)k0 * NH_ + n];
        float a1 = W1[(size_t)(k0 + 1) * NH_ + n];
        float a8 = W1[(size_t)(k0 + 8) * NH_ + n];
        float a9 = W1[(size_t)(k0 + 9) * NH_ + n];
        uint32_t h01, l01, h89, l89;
        split2(a0, a1, h01, l01);
        split2(a8, a9, h89, l89);
        g_Bpk[t] = make_uint4(h01, h89, l01, l89);
    } else if (tid < 128) {
        int s = bid - 256, o = tid;
        const float* base = W1 + (size_t)(HID_ + s * 64) * NH_ + o;
        float acc = 0.f;
#pragma unroll
        for (int d = 0; d < 64; d++) acc += base[d * NH_];
        g_S[s * NH_ + o] = acc;
    }
}

// ---------------- g1: C1 partials, sync-free mainloop with A prefetch ----------------
// grid (64, 4), block 256. CTA: 64 rows x 128 cols, K=256 (k-quarter).
__global__ void __launch_bounds__(256, 2) g1_mma(const float* __restrict__ hidden) {
    int tid = threadIdx.x, w = tid >> 5, lane = tid & 31;
    int q = lane & 3, r4 = lane >> 2;
    int rg = w >> 2, cq = w & 3;
    int bl0 = blockIdx.x * 64;
    int kq = blockIdx.y;

    float acc[2][4][4] = {};
    const float* rbase[2][2];
#pragma unroll
    for (int i = 0; i < 2; i++) {
        rbase[i][0] = hidden + (size_t)(bl0 + rg * 32 + i * 16 + r4) * HID_ + kq * 256 + q * 2;
        rbase[i][1] = rbase[i][0] + 8 * HID_;
    }

    float2 cv[2][4];
#pragma unroll
    for (int i = 0; i < 2; i++) {
        cv[i][0] = *(const float2*)(rbase[i][0]);
        cv[i][1] = *(const float2*)(rbase[i][0] + 8);
        cv[i][2] = *(const float2*)(rbase[i][1]);
        cv[i][3] = *(const float2*)(rbase[i][1] + 8);
    }

#pragma unroll 2
    for (int kl = 0; kl < 16; kl++) {
        float2 nv[2][4];
        if (kl < 15) {
#pragma unroll
            for (int i = 0; i < 2; i++) {
                nv[i][0] = *(const float2*)(rbase[i][0] + (kl + 1) * 16);
                nv[i][1] = *(const float2*)(rbase[i][0] + (kl + 1) * 16 + 8);
                nv[i][2] = *(const float2*)(rbase[i][1] + (kl + 1) * 16);
                nv[i][3] = *(const float2*)(rbase[i][1] + (kl + 1) * 16 + 8);
            }
        }
        uint32_t Ah[2][4], Al[2][4];
#pragma unroll
        for (int i = 0; i < 2; i++) {
            split2(cv[i][0].x, cv[i][0].y, Ah[i][0], Al[i][0]);
            split2(cv[i][2].x, cv[i][2].y, Ah[i][1], Al[i][1]);
            split2(cv[i][1].x, cv[i][1].y, Ah[i][2], Al[i][2]);
            split2(cv[i][3].x, cv[i][3].y, Ah[i][3], Al[i][3]);
        }
        const uint4* bq = g_Bpk + (size_t)(kq * 16 + kl) * 512 + cq * 128 + lane;
#pragma unroll
        for (int j = 0; j < 4; j++) {
            uint4 b = bq[j * 32];
#pragma unroll
            for (int i = 0; i < 2; i++) {
                mma16816(acc[i][j], Ah[i], b.x, b.y);
                mma16816(acc[i][j], Ah[i], b.z, b.w);
                mma16816(acc[i][j], Al[i], b.x, b.y);
            }
        }
#pragma unroll
        for (int i = 0; i < 2; i++)
#pragma unroll
            for (int e = 0; e < 4; e++) cv[i][e] = nv[i][e];
    }
    float* dst = g_C1p[kq];
#pragma unroll
    for (int i = 0; i < 2; i++) {
        int row0 = bl0 + rg * 32 + i * 16 + r4;
#pragma unroll
        for (int j = 0; j < 4; j++) {
            int col = cq * 32 + j * 8 + q * 2;
            *(float2*)&dst[(size_t)row0 * NH_ + col]       = make_float2(acc[i][j][0], acc[i][j][1]);
            *(float2*)&dst[(size_t)(row0 + 8) * NH_ + col] = make_float2(acc[i][j][2], acc[i][j][3]);
        }
    }
}

// ---------------- g2: branch GEMM + stat-GEMM ext kstep + fused epilogue ----------------
// grid 1024, block 256. CTA: 64 rows x 128 cols, K=256 + 16(ext).
__global__ void __launch_bounds__(256, 2) g2_mma(const float* __restrict__ br0,
                                                 const float* __restrict__ br1,
                                                 const float* __restrict__ br2,
                                                 const float* __restrict__ br3,
                                                 const float* __restrict__ b1,
                                                 const float* __restrict__ W2,
                                                 const float* __restrict__ b2v,
                                                 const float* __restrict__ epsf,
                                                 const float* __restrict__ temp,
                                                 float* __restrict__ out) {
    __shared__ uint4 sAh[4][4][32];     // 8 KB  [block][kstep][lane]
    __shared__ uint4 sAl[4][4][32];     // 8 KB
    __shared__ uint4 sBext[512];        // 8 KB  stat-S ext kstep, g_Bpk frag layout
    __shared__ float sC1[4 * NH_];      // 2 KB  (C1 sum + b1)
    __shared__ float sW2[NH_ * 4];      // 2 KB
    __shared__ float sST[64 * 12];      // 3 KB  finalized per-row stats
    __shared__ char  uBuf[2 * 64 * 12 * 4];  // 6 KB union: sSTp then sLog

    float (*sSTp)[64][12] = (float (*)[64][12])uBuf;   // raw per-k-half stat partials
    float (*sLog)[16]     = (float (*)[16])uBuf;       // [64][16] logit partials

    int tid = threadIdx.x, w = tid >> 5, lane = tid & 31;
    int q = lane & 3, r4 = lane >> 2;
    int rg = w >> 2, cq = w & 3;
    int th0 = blockIdx.x * 64;
    int cb = w & 3;         // convert: this warp's 16-row block
    int ckl = w >> 2;       // convert: base kstep (handles ckl and ckl+2)

    // ---- preload tables ----
    {
        size_t c0 = (size_t)(th0 >> 4) * NH_;
        for (int i = tid; i < 4 * NH_; i += 256)
            sC1[i] = g_C1p[0][c0 + i] + g_C1p[1][c0 + i] + g_C1p[2][c0 + i] + g_C1p[3][c0 + i]
                   + b1[i & 127];
    }
    for (int i = tid; i < NH_ * 4; i += 256) sW2[i] = W2[i];
    // build stat-S B-ext fragment (rows 0..11 = S, 12..15 = 0)
    for (int t = tid; t < 512; t += 256) {
        int qq = t & 3, n = t >> 2;
        int k0 = qq * 2;
        float v0 = (k0     < 12) ? g_S[(k0)     * NH_ + n] : 0.f;
        float v1 = (k0 + 1 < 12) ? g_S[(k0 + 1) * NH_ + n] : 0.f;
        float v8 = (k0 + 8 < 12) ? g_S[(k0 + 8) * NH_ + n] : 0.f;
        float v9 = (k0 + 9 < 12) ? g_S[(k0 + 9) * NH_ + n] : 0.f;
        uint32_t h01, l01, h89, l89;
        split2(v0, v1, h01, l01);
        split2(v8, v9, h89, l89);
        sBext[t] = make_uint4(h01, h89, l01, l89);
    }

    float acc[2][4][4] = {};

#pragma unroll 1
    for (int p = 0; p < 4; p++) {
        const float* bp = (p == 0) ? br0 : (p == 1) ? br1 : (p == 2) ? br2 : br3;
        // ---- convert phase ----
        float sum0 = 0.f, sq0 = 0.f, mx0 = -3.402823466e38f;
        float sum1 = 0.f, sq1 = 0.f, mx1 = -3.402823466e38f;
#pragma unroll
        for (int u = 0; u < 2; u++) {
            int kl = ckl + u * 2;
            const float* rp0 = bp + (size_t)(th0 + cb * 16 + r4) * 64 + kl * 16 + q * 2;
            const float* rp1 = rp0 + 8 * 64;
            float2 v00 = *(const float2*)(rp0);
            float2 v01 = *(const float2*)(rp0 + 8);
            float2 v10 = *(const float2*)(rp1);
            float2 v11 = *(const float2*)(rp1 + 8);
            uint4 hi, lo;
            split2(v00.x, v00.y, hi.x, lo.x);
            split2(v10.x, v10.y, hi.y, lo.y);
            split2(v01.x, v01.y, hi.z, lo.z);
            split2(v11.x, v11.y, hi.w, lo.w);
            sAh[cb][kl][lane] = hi;
            sAl[cb][kl][lane] = lo;
            sum0 += v00.x + v00.y + v01.x + v01.y;
            sq0 = fmaf(v00.x, v00.x, fmaf(v00.y, v00.y, fmaf(v01.x, v01.x, fmaf(v01.y, v01.y, sq0))));
            mx0 = fmaxf(mx0, fmaxf(fmaxf(v00.x, v00.y), fmaxf(v01.x, v01.y)));
            sum1 += v10.x + v10.y + v11.x + v11.y;
            sq1 = fmaf(v10.x, v10.x, fmaf(v10.y, v10.y, fmaf(v11.x, v11.x, fmaf(v11.y, v11.y, sq1))));
            mx1 = fmaxf(mx1, fmaxf(fmaxf(v10.x, v10.y), fmaxf(v11.x, v11.y)));
        }
#pragma unroll
        for (int m = 1; m <= 2; m <<= 1) {
            sum0 += __shfl_xor_sync(0xFFFFFFFFu, sum0, m);
            sq0  += __shfl_xor_sync(0xFFFFFFFFu, sq0,  m);
            mx0   = fmaxf(mx0, __shfl_xor_sync(0xFFFFFFFFu, mx0, m));
            sum1 += __shfl_xor_sync(0xFFFFFFFFu, sum1, m);
            sq1  += __shfl_xor_sync(0xFFFFFFFFu, sq1,  m);
            mx1   = fmaxf(mx1, __shfl_xor_sync(0xFFFFFFFFu, mx1, m));
        }
        if (q == 0) {
            sSTp[ckl][cb * 16 + r4][p * 3 + 0] = sum0;
            sSTp[ckl][cb * 16 + r4][p * 3 + 1] = sq0;
            sSTp[ckl][cb * 16 + r4][p * 3 + 2] = mx0;
            sSTp[ckl][cb * 16 + r4 + 8][p * 3 + 0] = sum1;
            sSTp[ckl][cb * 16 + r4 + 8][p * 3 + 1] = sq1;
            sSTp[ckl][cb * 16 + r4 + 8][p * 3 + 2] = mx1;
        }
        __syncthreads();
        // ---- mma phase ----
#pragma unroll
        for (int kl = 0; kl < 4; kl++) {
            uint4 ah0 = sAh[rg * 2][kl][lane];
            uint4 al0 = sAl[rg * 2][kl][lane];
            uint4 ah1 = sAh[rg * 2 + 1][kl][lane];
            uint4 al1 = sAl[rg * 2 + 1][kl][lane];
            const uint4* bq = g_Bpk + (size_t)(112 + p * 4 + kl) * 512 + cq * 128 + lane;
#pragma unroll
            for (int j = 0; j < 4; j++) {
                uint4 b = bq[j * 32];
                mma16816(acc[0][j], &ah0.x, b.x, b.y);
                mma16816(acc[0][j], &ah0.x, b.z, b.w);
                mma16816(acc[0][j], &al0.x, b.x, b.y);
                mma16816(acc[1][j], &ah1.x, b.x, b.y);
                mma16816(acc[1][j], &ah1.x, b.z, b.w);
                mma16816(acc[1][j], &al1.x, b.x, b.y);
            }
        }
        __syncthreads();
    }

    // ---- finalize stats ----
    if (tid < 64) {
#pragma unroll
        for (int p = 0; p < 4; p++) {
            float sa = sSTp[0][tid][p * 3 + 0] + sSTp[1][tid][p * 3 + 0];
            float sv = sSTp[0][tid][p * 3 + 1] + sSTp[1][tid][p * 3 + 1];
            float mv = fmaxf(sSTp[0][tid][p * 3 + 2], sSTp[1][tid][p * 3 + 2]);
            sST[tid * 12 + p * 3 + 0] = sa * (1.0f / 64.0f);
            sST[tid * 12 + p * 3 + 1] = sqrtf(fmaxf(sv * (1.0f / 64.0f), 1e-8f));
            sST[tid * 12 + p * 3 + 2] = mv;
        }
    }
    __syncthreads();

    // ---- build stat A-ext fragments (warps 0..3, block w) into sAh/sAl[w][0] ----
    if (w < 4) {
        int row0 = w * 16 + r4;
        int k0 = q * 2;
        float v0  = (k0     < 12) ? sST[row0 * 12 + k0]     : 0.f;
        float v1  = (k0 + 1 < 12) ? sST[row0 * 12 + k0 + 1] : 0.f;
        float v8  = (k0 + 8 < 12) ? sST[row0 * 12 + k0 + 8] : 0.f;
        float v9  = (k0 + 9 < 12) ? sST[row0 * 12 + k0 + 9] : 0.f;
        int row1 = row0 + 8;
        float u0  = (k0     < 12) ? sST[row1 * 12 + k0]     : 0.f;
        float u1  = (k0 + 1 < 12) ? sST[row1 * 12 + k0 + 1] : 0.f;
        float u8  = (k0 + 8 < 12) ? sST[row1 * 12 + k0 + 8] : 0.f;
        float u9  = (k0 + 9 < 12) ? sST[row1 * 12 + k0 + 9] : 0.f;
        uint4 hi, lo;
        split2(v0, v1, hi.x, lo.x);   // a0/a1: row r4, k q*2,q*2+1
        split2(u0, u1, hi.y, lo.y);   // row r4+8
        split2(v8, v9, hi.z, lo.z);   // row r4, k+8
        split2(u8, u9, hi.w, lo.w);   // row r4+8, k+8
        sAh[w][0][lane] = hi;
        sAl[w][0][lane] = lo;
    }
    __syncthreads();

    // ---- ext kstep: stat GEMM ----
    {
        uint4 ah0 = sAh[rg * 2][0][lane];
        uint4 al0 = sAl[rg * 2][0][lane];
        uint4 ah1 = sAh[rg * 2 + 1][0][lane];
        uint4 al1 = sAl[rg * 2 + 1][0][lane];
        const uint4* bq = sBext + cq * 128 + lane;
#pragma unroll
        for (int j = 0; j < 4; j++) {
            uint4 b = bq[j * 32];
            mma16816(acc[0][j], &ah0.x, b.x, b.y);
            mma16816(acc[0][j], &ah0.x, b.z, b.w);
            mma16816(acc[0][j], &al0.x, b.x, b.y);
            mma16816(acc[1][j], &ah1.x, b.x, b.y);
            mma16816(acc[1][j], &ah1.x, b.z, b.w);
            mma16816(acc[1][j], &al1.x, b.x, b.y);
        }
    }
    __syncthreads();   // before sLog overwrites the union buffer

    // ---- epilogue ----
    float pl[4][4];
#pragma unroll
    for (int s = 0; s < 4; s++)
#pragma unroll
        for (int c = 0; c < 4; c++) pl[s][c] = 0.f;

#pragma unroll
    for (int i = 0; i < 2; i++) {
#pragma unroll
        for (int rr = 0; rr < 2; rr++) {
            int rowc = rg * 32 + i * 16 + r4 + rr * 8;
            int bll = rowc >> 4;
            int slot = i * 2 + rr;
#pragma unroll
            for (int j = 0; j < 4; j++) {
#pragma unroll
                for (int e = 0; e < 2; e++) {
                    int col = cq * 32 + j * 8 + q * 2 + e;
                    float z = acc[i][j][rr * 2 + e] + sC1[bll * NH_ + col];
                    float g = 0.5f * z * (1.0f + erff(z * 0.70710678118654752440f));
                    pl[slot][0] = fmaf(g, sW2[col * 4 + 0], pl[slot][0]);
                    pl[slot][1] = fmaf(g, sW2[col * 4 + 1], pl[slot][1]);
                    pl[slot][2] = fmaf(g, sW2[col * 4 + 2], pl[slot][2]);
                    pl[slot][3] = fmaf(g, sW2[col * 4 + 3], pl[slot][3]);
                }
            }
        }
    }
#pragma unroll
    for (int m = 1; m <= 2; m <<= 1)
#pragma unroll
        for (int s = 0; s < 4; s++)
#pragma unroll
            for (int c = 0; c < 4; c++)
                pl[s][c] += __shfl_xor_sync(0xFFFFFFFFu, pl[s][c], m);
    if (q == 0) {
#pragma unroll
        for (int i = 0; i < 2; i++)
#pragma unroll
            for (int rr = 0; rr < 2; rr++) {
                int rowc = rg * 32 + i * 16 + r4 + rr * 8;
                int slot = i * 2 + rr;
#pragma unroll
                for (int c = 0; c < 4; c++)
                    sLog[rowc][cq * 4 + c] = pl[slot][c];
            }
    }
    __syncthreads();

    if (tid < 64) {
        int th = th0 + tid;
        int h = th & (H_ - 1);
        float l0 = sLog[tid][0] + sLog[tid][4] + sLog[tid][8]  + sLog[tid][12] + b2v[0];
        float l1 = sLog[tid][1] + sLog[tid][5] + sLog[tid][9]  + sLog[tid][13] + b2v[1];
        float l2 = sLog[tid][2] + sLog[tid][6] + sLog[tid][10] + sLog[tid][14] + b2v[2];
        float l3 = sLog[tid][3] + sLog[tid][7] + sLog[tid][11] + sLog[tid][15] + b2v[3];
        float t = fminf(fmaxf(temp[h], 0.2f), 10.0f);
        float inv_t = 1.0f / t;
        float mx = fmaxf(fmaxf(l0, l1), fmaxf(l2, l3));
        float e0 = expf((l0 - mx) * inv_t);
        float e1 = expf((l1 - mx) * inv_t);
        float e2 = expf((l2 - mx) * inv_t);
        float e3 = expf((l3 - mx) * inv_t);
        float inv = 1.0f / (e0 + e1 + e2 + e3);
        float w0 = e0 * inv, w1 = e1 * inv, w2 = e2 * inv, w3 = e3 * inv;
        float f0 = fminf(fmaxf(epsf[h * 4 + 0], 1e-7f), 0.1f);
        float f1 = fminf(fmaxf(epsf[h * 4 + 1], 1e-7f), 0.1f);
        float f2 = fminf(fmaxf(epsf[h * 4 + 2], 1e-7f), 0.1f);
        float f3 = fminf(fmaxf(epsf[h * 4 + 3], 1e-7f), 0.1f);
        w0 = fmaxf(w0, f0); w1 = fmaxf(w1, f1); w2 = fmaxf(w2, f2); w3 = fmaxf(w3, f3);
        float inv2 = 1.0f / (w0 + w1 + w2 + w3);
        ((float4*)out)[th] = make_float4(w0 * inv2, w1 * inv2, w2 * inv2, w3 * inv2);
    }
}

// ---------------- launch ----------------
extern "C" void kernel_launch(void* const* d_in, const int* in_sizes, int n_in,
                              void* d_out, int out_size) {
    const float* hidden = (const float*)d_in[0];
    const float* br0    = (const float*)d_in[1];
    const float* br1    = (const float*)d_in[2];
    const float* br2    = (const float*)d_in[3];
    const float* br3    = (const float*)d_in[4];
    const float* W1     = (const float*)d_in[5];
    const float* b1     = (const float*)d_in[6];
    const float* W2     = (const float*)d_in[7];
    const float* b2v    = (const float*)d_in[8];
    const float* epsf   = (const float*)d_in[9];
    const float* temp   = (const float*)d_in[10];
    float* out = (float*)d_out;

    prep_kernel<<<268, 256>>>(W1);
    g1_mma<<<dim3(64, 4), 256>>>(hidden);
    g2_mma<<<1024, 256>>>(br0, br1, br2, br3, b1, W2, b2v, epsf, temp, out);
}

// round 13
// speedup vs baseline: 5.2564x; 1.0422x over previous
#include <cuda_runtime.h>
#include <cuda_bf16.h>
#include <math.h>
#include <stdint.h>

#define H_   16
#define HID_ 1024
#define BL_  4096      /* B*L   */
#define TH_  65536     /* B*L*H */
#define NH_  128       /* gate hidden = 2*D */

// ---------------- device scratch (no allocations) ----------------
// B packed in m16n8k16 fragment order: [ks][n][q] -> uint4 (b0h, b1h, b0l, b1l)
__device__ uint4 g_Bpk[128 * 512];              // 1 MB (128 ksteps over K=2048)
__device__ float g_S[12 * NH_];                 // stat-block column sums
__device__ float g_C1p[4][BL_ * NH_];           // hidden@W1 k-quarter partials (8 MB)

// ---------------- helpers ----------------
__device__ __forceinline__ uint32_t packbf2(float x, float y) {
    __nv_bfloat162 t = __floats2bfloat162_rn(x, y);
    return *(uint32_t*)&t;
}
__device__ __forceinline__ void split2(float x, float y, uint32_t& hi, uint32_t& lo) {
    __nv_bfloat16 hx = __float2bfloat16_rn(x);
    __nv_bfloat16 hy = __float2bfloat16_rn(y);
    __nv_bfloat162 hh = __halves2bfloat162(hx, hy);
    hi = *(uint32_t*)&hh;
    lo = packbf2(x - __bfloat162float(hx), y - __bfloat162float(hy));
}
__device__ __forceinline__ void mma16816(float* d, const uint32_t* a, uint32_t b0, uint32_t b1) {
    asm volatile(
        "mma.sync.aligned.m16n8k16.row.col.f32.bf16.bf16.f32 "
        "{%0,%1,%2,%3}, {%4,%5,%6,%7}, {%8,%9}, {%0,%1,%2,%3};"
        : "+f"(d[0]), "+f"(d[1]), "+f"(d[2]), "+f"(d[3])
        : "r"(a[0]), "r"(a[1]), "r"(a[2]), "r"(a[3]), "r"(b0), "r"(b1));
}

// ---------------- prep (merged): packB (blocks 0..255) + S sums (blocks 256..267) ----------------
__global__ void prep_kernel(const float* __restrict__ W1) {
    int bid = blockIdx.x, tid = threadIdx.x;
    if (bid < 256) {
        int t = bid * 256 + tid;   // 65536
        int q = t & 3, n = (t >> 2) & 127, ks = t >> 9;
        int k0 = ks * 16 + q * 2;
        float a0 = W1[(size_t)k0 * NH_ + n];
        float a1 = W1[(size_t)(k0 + 1) * NH_ + n];
        float a8 = W1[(size_t)(k0 + 8) * NH_ + n];
        float a9 = W1[(size_t)(k0 + 9) * NH_ + n];
        uint32_t h01, l01, h89, l89;
        split2(a0, a1, h01, l01);
        split2(a8, a9, h89, l89);
        g_Bpk[t] = make_uint4(h01, h89, l01, l89);
    } else if (tid < 128) {
        int s = bid - 256, o = tid;
        const float* base = W1 + (size_t)(HID_ + s * 64) * NH_ + o;
        float acc = 0.f;
#pragma unroll
        for (int d = 0; d < 64; d++) acc += base[d * NH_];
        g_S[s * NH_ + o] = acc;
    }
}

// ---------------- g1: C1 partials. One warp = 16 rows x 128 cols. No syncs, no redundant converts. ----------------
// grid (64, 4), block 128. CTA: 64 rows; K=256 (k-quarter kq).
__global__ void __launch_bounds__(128, 2) g1_mma(const float* __restrict__ hidden) {
    int tid = threadIdx.x, w = tid >> 5, lane = tid & 31;
    int q = lane & 3, r4 = lane >> 2;
    int kq = blockIdx.y;
    int row0 = blockIdx.x * 64 + w * 16 + r4;
    const float* rb0 = hidden + (size_t)row0 * HID_ + kq * 256 + q * 2;
    const float* rb1 = rb0 + 8 * HID_;

    float acc[16][4];
#pragma unroll
    for (int j = 0; j < 16; j++)
#pragma unroll
        for (int e = 0; e < 4; e++) acc[j][e] = 0.f;

    float2 cv[4];
    cv[0] = *(const float2*)(rb0);
    cv[1] = *(const float2*)(rb0 + 8);
    cv[2] = *(const float2*)(rb1);
    cv[3] = *(const float2*)(rb1 + 8);

#pragma unroll 2
    for (int kl = 0; kl < 16; kl++) {
        float2 nv[4];
        if (kl < 15) {
            nv[0] = *(const float2*)(rb0 + (kl + 1) * 16);
            nv[1] = *(const float2*)(rb0 + (kl + 1) * 16 + 8);
            nv[2] = *(const float2*)(rb1 + (kl + 1) * 16);
            nv[3] = *(const float2*)(rb1 + (kl + 1) * 16 + 8);
        }
        uint32_t Ah[4], Al[4];
        split2(cv[0].x, cv[0].y, Ah[0], Al[0]);
        split2(cv[2].x, cv[2].y, Ah[1], Al[1]);
        split2(cv[1].x, cv[1].y, Ah[2], Al[2]);
        split2(cv[3].x, cv[3].y, Ah[3], Al[3]);
        const uint4* bq = g_Bpk + (size_t)(kq * 16 + kl) * 512 + lane;
#pragma unroll
        for (int j = 0; j < 16; j++) {
            uint4 b = bq[j * 32];
            mma16816(acc[j], Ah, b.x, b.y);
            mma16816(acc[j], Ah, b.z, b.w);
            mma16816(acc[j], Al, b.x, b.y);
        }
#pragma unroll
        for (int e = 0; e < 4; e++) cv[e] = nv[e];
    }
    float* dst = g_C1p[kq];
#pragma unroll
    for (int j = 0; j < 16; j++) {
        int col = j * 8 + q * 2;
        *(float2*)&dst[(size_t)row0 * NH_ + col]       = make_float2(acc[j][0], acc[j][1]);
        *(float2*)&dst[(size_t)(row0 + 8) * NH_ + col] = make_float2(acc[j][2], acc[j][3]);
    }
}

// ---------------- g2: branch GEMM + stat-GEMM ext kstep + fused epilogue, pipelined loads ----------------
// grid 1024, block 256. CTA: 64 rows x 128 cols, K=256 + 16(ext).
__global__ void __launch_bounds__(256, 2) g2_mma(const float* __restrict__ br0,
                                                 const float* __restrict__ br1,
                                                 const float* __restrict__ br2,
                                                 const float* __restrict__ br3,
                                                 const float* __restrict__ b1,
                                                 const float* __restrict__ W2,
                                                 const float* __restrict__ b2v,
                                                 const float* __restrict__ epsf,
                                                 const float* __restrict__ temp,
                                                 float* __restrict__ out) {
    __shared__ uint4 sAh[4][4][32];     // 8 KB  [block][kstep][lane]
    __shared__ uint4 sAl[4][4][32];     // 8 KB
    __shared__ uint4 sBext[512];        // 8 KB  stat-S ext kstep, g_Bpk frag layout
    __shared__ float sC1[4 * NH_];      // 2 KB  (C1 sum + b1)
    __shared__ float sW2[NH_ * 4];      // 2 KB
    __shared__ float sST[64 * 12];      // 3 KB  finalized per-row stats
    __shared__ char  uBuf[2 * 64 * 12 * 4];  // 6 KB union: sSTp then sLog

    float (*sSTp)[64][12] = (float (*)[64][12])uBuf;   // raw per-k-half stat partials
    float (*sLog)[16]     = (float (*)[16])uBuf;       // [64][16] logit partials

    int tid = threadIdx.x, w = tid >> 5, lane = tid & 31;
    int q = lane & 3, r4 = lane >> 2;
    int rg = w >> 2, cq = w & 3;
    int th0 = blockIdx.x * 64;
    int cb = w & 3;         // convert: this warp's 16-row block
    int ckl = w >> 2;       // convert: base kstep (handles ckl and ckl+2)

    // convert-source base offsets (constant across branches)
    size_t coff0 = (size_t)(th0 + cb * 16 + r4) * 64 + ckl * 16 + q * 2;
    size_t coff1 = coff0 + 8 * 64;

    // ---- preload tables ----
    {
        size_t c0 = (size_t)(th0 >> 4) * NH_;
        for (int i = tid; i < 4 * NH_; i += 256)
            sC1[i] = g_C1p[0][c0 + i] + g_C1p[1][c0 + i] + g_C1p[2][c0 + i] + g_C1p[3][c0 + i]
                   + b1[i & 127];
    }
    for (int i = tid; i < NH_ * 4; i += 256) sW2[i] = W2[i];
    // build stat-S B-ext fragment (rows 0..11 = S, 12..15 = 0)
    for (int t = tid; t < 512; t += 256) {
        int qq = t & 3, n = t >> 2;
        int k0 = qq * 2;
        float v0 = (k0     < 12) ? g_S[(k0)     * NH_ + n] : 0.f;
        float v1 = (k0 + 1 < 12) ? g_S[(k0 + 1) * NH_ + n] : 0.f;
        float v8 = (k0 + 8 < 12) ? g_S[(k0 + 8) * NH_ + n] : 0.f;
        float v9 = (k0 + 9 < 12) ? g_S[(k0 + 9) * NH_ + n] : 0.f;
        uint32_t h01, l01, h89, l89;
        split2(v0, v1, h01, l01);
        split2(v8, v9, h89, l89);
        sBext[t] = make_uint4(h01, h89, l01, l89);
    }

    float acc[2][4][4] = {};

    // ---- prefetch branch 0 convert values ----
    float2 pv[2][4];
#pragma unroll
    for (int u = 0; u < 2; u++) {
        const float* rp0 = br0 + coff0 + u * 32;
        const float* rp1 = br0 + coff1 + u * 32;
        pv[u][0] = *(const float2*)(rp0);
        pv[u][1] = *(const float2*)(rp0 + 8);
        pv[u][2] = *(const float2*)(rp1);
        pv[u][3] = *(const float2*)(rp1 + 8);
    }

#pragma unroll 1
    for (int p = 0; p < 4; p++) {
        // ---- convert phase (from prefetched registers) ----
        float sum0 = 0.f, sq0 = 0.f, mx0 = -3.402823466e38f;
        float sum1 = 0.f, sq1 = 0.f, mx1 = -3.402823466e38f;
#pragma unroll
        for (int u = 0; u < 2; u++) {
            int kl = ckl + u * 2;
            float2 v00 = pv[u][0], v01 = pv[u][1], v10 = pv[u][2], v11 = pv[u][3];
            uint4 hi, lo;
            split2(v00.x, v00.y, hi.x, lo.x);
            split2(v10.x, v10.y, hi.y, lo.y);
            split2(v01.x, v01.y, hi.z, lo.z);
            split2(v11.x, v11.y, hi.w, lo.w);
            sAh[cb][kl][lane] = hi;
            sAl[cb][kl][lane] = lo;
            sum0 += v00.x + v00.y + v01.x + v01.y;
            sq0 = fmaf(v00.x, v00.x, fmaf(v00.y, v00.y, fmaf(v01.x, v01.x, fmaf(v01.y, v01.y, sq0))));
            mx0 = fmaxf(mx0, fmaxf(fmaxf(v00.x, v00.y), fmaxf(v01.x, v01.y)));
            sum1 += v10.x + v10.y + v11.x + v11.y;
            sq1 = fmaf(v10.x, v10.x, fmaf(v10.y, v10.y, fmaf(v11.x, v11.x, fmaf(v11.y, v11.y, sq1))));
            mx1 = fmaxf(mx1, fmaxf(fmaxf(v10.x, v10.y), fmaxf(v11.x, v11.y)));
        }
#pragma unroll
        for (int m = 1; m <= 2; m <<= 1) {
            sum0 += __shfl_xor_sync(0xFFFFFFFFu, sum0, m);
            sq0  += __shfl_xor_sync(0xFFFFFFFFu, sq0,  m);
            mx0   = fmaxf(mx0, __shfl_xor_sync(0xFFFFFFFFu, mx0, m));
            sum1 += __shfl_xor_sync(0xFFFFFFFFu, sum1, m);
            sq1  += __shfl_xor_sync(0xFFFFFFFFu, sq1,  m);
            mx1   = fmaxf(mx1, __shfl_xor_sync(0xFFFFFFFFu, mx1, m));
        }
        if (q == 0) {
            sSTp[ckl][cb * 16 + r4][p * 3 + 0] = sum0;
            sSTp[ckl][cb * 16 + r4][p * 3 + 1] = sq0;
            sSTp[ckl][cb * 16 + r4][p * 3 + 2] = mx0;
            sSTp[ckl][cb * 16 + r4 + 8][p * 3 + 0] = sum1;
            sSTp[ckl][cb * 16 + r4 + 8][p * 3 + 1] = sq1;
            sSTp[ckl][cb * 16 + r4 + 8][p * 3 + 2] = mx1;
        }
        __syncthreads();
        // ---- issue next branch's loads (in flight during mma phase) ----
        if (p < 3) {
            const float* bp = (p == 0) ? br1 : (p == 1) ? br2 : br3;
#pragma unroll
            for (int u = 0; u < 2; u++) {
                const float* rp0 = bp + coff0 + u * 32;
                const float* rp1 = bp + coff1 + u * 32;
                pv[u][0] = *(const float2*)(rp0);
                pv[u][1] = *(const float2*)(rp0 + 8);
                pv[u][2] = *(const float2*)(rp1);
                pv[u][3] = *(const float2*)(rp1 + 8);
            }
        }
        // ---- mma phase ----
#pragma unroll
        for (int kl = 0; kl < 4; kl++) {
            uint4 ah0 = sAh[rg * 2][kl][lane];
            uint4 al0 = sAl[rg * 2][kl][lane];
            uint4 ah1 = sAh[rg * 2 + 1][kl][lane];
            uint4 al1 = sAl[rg * 2 + 1][kl][lane];
            const uint4* bq = g_Bpk + (size_t)(112 + p * 4 + kl) * 512 + cq * 128 + lane;
#pragma unroll
            for (int j = 0; j < 4; j++) {
                uint4 b = bq[j * 32];
                mma16816(acc[0][j], &ah0.x, b.x, b.y);
                mma16816(acc[0][j], &ah0.x, b.z, b.w);
                mma16816(acc[0][j], &al0.x, b.x, b.y);
                mma16816(acc[1][j], &ah1.x, b.x, b.y);
                mma16816(acc[1][j], &ah1.x, b.z, b.w);
                mma16816(acc[1][j], &al1.x, b.x, b.y);
            }
        }
        __syncthreads();
    }

    // ---- finalize stats ----
    if (tid < 64) {
#pragma unroll
        for (int p = 0; p < 4; p++) {
            float sa = sSTp[0][tid][p * 3 + 0] + sSTp[1][tid][p * 3 + 0];
            float sv = sSTp[0][tid][p * 3 + 1] + sSTp[1][tid][p * 3 + 1];
            float mv = fmaxf(sSTp[0][tid][p * 3 + 2], sSTp[1][tid][p * 3 + 2]);
            sST[tid * 12 + p * 3 + 0] = sa * (1.0f / 64.0f);
            sST[tid * 12 + p * 3 + 1] = sqrtf(fmaxf(sv * (1.0f / 64.0f), 1e-8f));
            sST[tid * 12 + p * 3 + 2] = mv;
        }
    }
    __syncthreads();

    // ---- build stat A-ext fragments (warps 0..3, block w) into sAh/sAl[w][0] ----
    if (w < 4) {
        int row0 = w * 16 + r4;
        int k0 = q * 2;
        float v0  = (k0     < 12) ? sST[row0 * 12 + k0]     : 0.f;
        float v1  = (k0 + 1 < 12) ? sST[row0 * 12 + k0 + 1] : 0.f;
        float v8  = (k0 + 8 < 12) ? sST[row0 * 12 + k0 + 8] : 0.f;
        float v9  = (k0 + 9 < 12) ? sST[row0 * 12 + k0 + 9] : 0.f;
        int row1 = row0 + 8;
        float u0  = (k0     < 12) ? sST[row1 * 12 + k0]     : 0.f;
        float u1  = (k0 + 1 < 12) ? sST[row1 * 12 + k0 + 1] : 0.f;
        float u8  = (k0 + 8 < 12) ? sST[row1 * 12 + k0 + 8] : 0.f;
        float u9  = (k0 + 9 < 12) ? sST[row1 * 12 + k0 + 9] : 0.f;
        uint4 hi, lo;
        split2(v0, v1, hi.x, lo.x);
        split2(u0, u1, hi.y, lo.y);
        split2(v8, v9, hi.z, lo.z);
        split2(u8, u9, hi.w, lo.w);
        sAh[w][0][lane] = hi;
        sAl[w][0][lane] = lo;
    }
    __syncthreads();

    // ---- ext kstep: stat GEMM ----
    {
        uint4 ah0 = sAh[rg * 2][0][lane];
        uint4 al0 = sAl[rg * 2][0][lane];
        uint4 ah1 = sAh[rg * 2 + 1][0][lane];
        uint4 al1 = sAl[rg * 2 + 1][0][lane];
        const uint4* bq = sBext + cq * 128 + lane;
#pragma unroll
        for (int j = 0; j < 4; j++) {
            uint4 b = bq[j * 32];
            mma16816(acc[0][j], &ah0.x, b.x, b.y);
            mma16816(acc[0][j], &ah0.x, b.z, b.w);
            mma16816(acc[0][j], &al0.x, b.x, b.y);
            mma16816(acc[1][j], &ah1.x, b.x, b.y);
            mma16816(acc[1][j], &ah1.x, b.z, b.w);
            mma16816(acc[1][j], &al1.x, b.x, b.y);
        }
    }
    __syncthreads();   // before sLog overwrites the union buffer

    // ---- epilogue ----
    float pl[4][4];
#pragma unroll
    for (int s = 0; s < 4; s++)
#pragma unroll
        for (int c = 0; c < 4; c++) pl[s][c] = 0.f;

#pragma unroll
    for (int i = 0; i < 2; i++) {
#pragma unroll
        for (int rr = 0; rr < 2; rr++) {
            int rowc = rg * 32 + i * 16 + r4 + rr * 8;
            int bll = rowc >> 4;
            int slot = i * 2 + rr;
#pragma unroll
            for (int j = 0; j < 4; j++) {
#pragma unroll
                for (int e = 0; e < 2; e++) {
                    int col = cq * 32 + j * 8 + q * 2 + e;
                    float z = acc[i][j][rr * 2 + e] + sC1[bll * NH_ + col];
                    float g = 0.5f * z * (1.0f + erff(z * 0.70710678118654752440f));
                    pl[slot][0] = fmaf(g, sW2[col * 4 + 0], pl[slot][0]);
                    pl[slot][1] = fmaf(g, sW2[col * 4 + 1], pl[slot][1]);
                    pl[slot][2] = fmaf(g, sW2[col * 4 + 2], pl[slot][2]);
                    pl[slot][3] = fmaf(g, sW2[col * 4 + 3], pl[slot][3]);
                }
            }
        }
    }
#pragma unroll
    for (int m = 1; m <= 2; m <<= 1)
#pragma unroll
        for (int s = 0; s < 4; s++)
#pragma unroll
            for (int c = 0; c < 4; c++)
                pl[s][c] += __shfl_xor_sync(0xFFFFFFFFu, pl[s][c], m);
    if (q == 0) {
#pragma unroll
        for (int i = 0; i < 2; i++)
#pragma unroll
            for (int rr = 0; rr < 2; rr++) {
                int rowc = rg * 32 + i * 16 + r4 + rr * 8;
                int slot = i * 2 + rr;
#pragma unroll
                for (int c = 0; c < 4; c++)
                    sLog[rowc][cq * 4 + c] = pl[slot][c];
            }
    }
    __syncthreads();

    if (tid < 64) {
        int th = th0 + tid;
        int h = th & (H_ - 1);
        float l0 = sLog[tid][0] + sLog[tid][4] + sLog[tid][8]  + sLog[tid][12] + b2v[0];
        float l1 = sLog[tid][1] + sLog[tid][5] + sLog[tid][9]  + sLog[tid][13] + b2v[1];
        float l2 = sLog[tid][2] + sLog[tid][6] + sLog[tid][10] + sLog[tid][14] + b2v[2];
        float l3 = sLog[tid][3] + sLog[tid][7] + sLog[tid][11] + sLog[tid][15] + b2v[3];
        float t = fminf(fmaxf(temp[h], 0.2f), 10.0f);
        float inv_t = 1.0f / t;
        float mx = fmaxf(fmaxf(l0, l1), fmaxf(l2, l3));
        float e0 = expf((l0 - mx) * inv_t);
        float e1 = expf((l1 - mx) * inv_t);
        float e2 = expf((l2 - mx) * inv_t);
        float e3 = expf((l3 - mx) * inv_t);
        float inv = 1.0f / (e0 + e1 + e2 + e3);
        float w0 = e0 * inv, w1 = e1 * inv, w2 = e2 * inv, w3 = e3 * inv;
        float f0 = fminf(fmaxf(epsf[h * 4 + 0], 1e-7f), 0.1f);
        float f1 = fminf(fmaxf(epsf[h * 4 + 1], 1e-7f), 0.1f);
        float f2 = fminf(fmaxf(epsf[h * 4 + 2], 1e-7f), 0.1f);
        float f3 = fminf(fmaxf(epsf[h * 4 + 3], 1e-7f), 0.1f);
        w0 = fmaxf(w0, f0); w1 = fmaxf(w1, f1); w2 = fmaxf(w2, f2); w3 = fmaxf(w3, f3);
        float inv2 = 1.0f / (w0 + w1 + w2 + w3);
        ((float4*)out)[th] = make_float4(w0 * inv2, w1 * inv2, w2 * inv2, w3 * inv2);
    }
}

// ---------------- launch ----------------
extern "C" void kernel_launch(void* const* d_in, const int* in_sizes, int n_in,
                              void* d_out, int out_size) {
    const float* hidden = (const float*)d_in[0];
    const float* br0    = (const float*)d_in[1];
    const float* br1    = (const float*)d_in[2];
    const float* br2    = (const float*)d_in[3];
    const float* br3    = (const float*)d_in[4];
    const float* W1     = (const float*)d_in[5];
    const float* b1     = (const float*)d_in[6];
    const float* W2     = (const float*)d_in[7];
    const float* b2v    = (const float*)d_in[8];
    const float* epsf   = (const float*)d_in[9];
    const float* temp   = (const float*)d_in[10];
    float* out = (float*)d_out;

    prep_kernel<<<268, 256>>>(W1);
    g1_mma<<<dim3(64, 4), 128>>>(hidden);
    g2_mma<<<1024, 256>>>(br0, br1, br2, br3, b1, W2, b2v, epsf, temp, out);
}